// round 1
// baseline (speedup 1.0000x reference)
#include <cuda_runtime.h>

#define S_LEN  2048
#define BATCH  2
#define HID    1024
#define NHEAD  16
#define HDIM   64
#define NLAYER 12
#define M_ROWS (S_LEN*BATCH)   // 4096
#define ROWB   (BATCH*HID)     // 2048 floats per s-step

// ---------------- scratch (no cudaMalloc allowed) ----------------
__device__ float g_x  [M_ROWS*HID];
__device__ float g_q  [M_ROWS*HID];
__device__ float g_k  [M_ROWS*HID];
__device__ float g_v  [M_ROWS*HID];
__device__ float g_ctx[M_ROWS*HID];
__device__ float g_y  [M_ROWS*HID];

// =================================================================
// SGEMM: C[4096][1024] = A[4096][1024] @ W[1024][1024] + bias (+res)
// 128x128 block tile, 256 threads, 8x8 per thread, K-tile 8.
// =================================================================
__device__ __forceinline__ void sgemm_body(
    const float* __restrict__ A, const float* __restrict__ W,
    const float* __restrict__ bias, const float* __restrict__ res,
    float* __restrict__ C, int bx, int by)
{
    __shared__ float As[8][132];   // A^T tile, padded
    __shared__ float Bs[8][128];

    const int t  = threadIdx.x;
    const int tx = t & 15, ty = t >> 4;
    const int m0 = by * 128;
    const int n0 = bx * 128;

    const int lm = t >> 1;          // 0..127
    const int lk = (t & 1) * 4;     // 0 / 4
    const int bk = t >> 5;          // 0..7
    const int bn = (t & 31) * 4;    // 0..124

    float acc[8][8];
#pragma unroll
    for (int i = 0; i < 8; i++)
#pragma unroll
        for (int j = 0; j < 8; j++) acc[i][j] = 0.f;

    const float* Aptr = A + (size_t)(m0 + lm) * HID + lk;
    const float* Wptr = W + (size_t)bk * HID + n0 + bn;

    for (int k0 = 0; k0 < HID; k0 += 8) {
        float4 a4 = *(const float4*)(Aptr + k0);
        float4 b4 = *(const float4*)(Wptr + (size_t)k0 * HID);
        As[lk+0][lm] = a4.x; As[lk+1][lm] = a4.y;
        As[lk+2][lm] = a4.z; As[lk+3][lm] = a4.w;
        *(float4*)&Bs[bk][bn] = b4;
        __syncthreads();
#pragma unroll
        for (int kk = 0; kk < 8; kk++) {
            float a[8], b[8];
            float4 t0 = *(const float4*)&As[kk][ty*4];
            float4 t1 = *(const float4*)&As[kk][64 + ty*4];
            a[0]=t0.x; a[1]=t0.y; a[2]=t0.z; a[3]=t0.w;
            a[4]=t1.x; a[5]=t1.y; a[6]=t1.z; a[7]=t1.w;
            float4 u0 = *(const float4*)&Bs[kk][tx*4];
            float4 u1 = *(const float4*)&Bs[kk][64 + tx*4];
            b[0]=u0.x; b[1]=u0.y; b[2]=u0.z; b[3]=u0.w;
            b[4]=u1.x; b[5]=u1.y; b[6]=u1.z; b[7]=u1.w;
#pragma unroll
            for (int i = 0; i < 8; i++)
#pragma unroll
                for (int j = 0; j < 8; j++)
                    acc[i][j] += a[i] * b[j];
        }
        __syncthreads();
    }

#pragma unroll
    for (int ii = 0; ii < 2; ii++)
#pragma unroll
    for (int i = 0; i < 4; i++) {
        int m = m0 + ii*64 + ty*4 + i;
        float* crow = C + (size_t)m * HID;
        const float* rrow = res ? res + (size_t)m * HID : nullptr;
#pragma unroll
        for (int jj = 0; jj < 2; jj++) {
            int n = n0 + jj*64 + tx*4;
            float4 o;
            o.x = acc[ii*4+i][jj*4+0] + bias[n+0];
            o.y = acc[ii*4+i][jj*4+1] + bias[n+1];
            o.z = acc[ii*4+i][jj*4+2] + bias[n+2];
            o.w = acc[ii*4+i][jj*4+3] + bias[n+3];
            if (rrow) {
                float4 rv = *(const float4*)(rrow + n);
                o.x += rv.x; o.y += rv.y; o.z += rv.z; o.w += rv.w;
            }
            *(float4*)(crow + n) = o;
        }
    }
}

__global__ __launch_bounds__(256, 2)
void sgemm_kernel(const float* __restrict__ A, const float* __restrict__ W,
                  const float* __restrict__ bias, const float* __restrict__ res,
                  float* __restrict__ C)
{
    sgemm_body(A, W, bias, res, C, blockIdx.x, blockIdx.y);
}

__global__ __launch_bounds__(256, 2)
void qkv_gemm_kernel(const float* __restrict__ X,
                     const float* __restrict__ W0, const float* __restrict__ W1, const float* __restrict__ W2,
                     const float* __restrict__ b0, const float* __restrict__ b1, const float* __restrict__ b2,
                     float* __restrict__ O0, float* __restrict__ O1, float* __restrict__ O2)
{
    const float* W; const float* bi; float* O;
    if (blockIdx.z == 0)      { W = W0; bi = b0; O = O0; }
    else if (blockIdx.z == 1) { W = W1; bi = b1; O = O1; }
    else                      { W = W2; bi = b2; O = O2; }
    sgemm_body(X, W, bi, nullptr, O, blockIdx.x, blockIdx.y);
}

// =================================================================
// Fused flash-style attention (fp32, online softmax)
// grid: (S/64, B*NH), 256 threads, 64-query x 64-key tiles, HD=64
// smem: Qs[d][q] (65), KPs = K[d][k] then P[k][q] (65), Vs[k][d] (68)
// =================================================================
#define QS_STRIDE 65
#define VS_STRIDE 68
#define ATTN_SMEM ((2*64*QS_STRIDE + 64*VS_STRIDE) * (int)sizeof(float))  // 50688 B

__global__ __launch_bounds__(256)
void attn_kernel(const float* __restrict__ Q, const float* __restrict__ K,
                 const float* __restrict__ V, const float* __restrict__ mask,
                 float* __restrict__ O)
{
    extern __shared__ float sm[];
    float* Qs  = sm;                       // 64*65
    float* KPs = sm + 64*QS_STRIDE;        // 64*65
    float* Vs  = sm + 2*64*QS_STRIDE;      // 64*68

    const int t  = threadIdx.x;
    const int tx = t & 15, ty = t >> 4;
    const int s0 = blockIdx.x * 64;
    const int b  = blockIdx.y / NHEAD;
    const int h  = blockIdx.y % NHEAD;
    const int base = b * HID + h * HDIM;
    const float scale = 0.125f;            // 1/sqrt(64)

    // load Q tile, pre-scaled, transposed to [d][q]
    for (int idx = t; idx < 64*16; idx += 256) {
        int row = idx >> 4;
        int dv  = (idx & 15) * 4;
        float4 qv = *(const float4*)(Q + (size_t)(s0+row)*ROWB + base + dv);
        Qs[(dv+0)*QS_STRIDE + row] = qv.x * scale;
        Qs[(dv+1)*QS_STRIDE + row] = qv.y * scale;
        Qs[(dv+2)*QS_STRIDE + row] = qv.z * scale;
        Qs[(dv+3)*QS_STRIDE + row] = qv.w * scale;
    }

    float acc[4][4], mrow[4], lrow[4];
#pragma unroll
    for (int i = 0; i < 4; i++) {
        mrow[i] = -1e30f; lrow[i] = 0.f;
#pragma unroll
        for (int j = 0; j < 4; j++) acc[i][j] = 0.f;
    }

    for (int kt = 0; kt < S_LEN/64; kt++) {
        const int k0 = kt * 64;
        __syncthreads();   // covers Q load (1st iter) + prev-iter P/V reads
        for (int idx = t; idx < 64*16; idx += 256) {
            int row = idx >> 4;
            int dv  = (idx & 15) * 4;
            float4 kv = *(const float4*)(K + (size_t)(k0+row)*ROWB + base + dv);
            KPs[(dv+0)*QS_STRIDE + row] = kv.x;
            KPs[(dv+1)*QS_STRIDE + row] = kv.y;
            KPs[(dv+2)*QS_STRIDE + row] = kv.z;
            KPs[(dv+3)*QS_STRIDE + row] = kv.w;
            float4 vv = *(const float4*)(V + (size_t)(k0+row)*ROWB + base + dv);
            *(float4*)&Vs[row*VS_STRIDE + dv] = vv;
        }
        __syncthreads();

        // scores: s = Qscaled . K + mask
        float s[4][4];
        float maskv[4];
#pragma unroll
        for (int j = 0; j < 4; j++)
            maskv[j] = mask[(size_t)b*S_LEN + k0 + tx*4 + j];
#pragma unroll
        for (int i = 0; i < 4; i++)
#pragma unroll
            for (int j = 0; j < 4; j++) s[i][j] = maskv[j];

#pragma unroll 8
        for (int d = 0; d < 64; d++) {
            float a[4], bb[4];
#pragma unroll
            for (int i = 0; i < 4; i++) a[i]  = Qs [d*QS_STRIDE + ty*4 + i];
#pragma unroll
            for (int j = 0; j < 4; j++) bb[j] = KPs[d*QS_STRIDE + tx*4 + j];
#pragma unroll
            for (int i = 0; i < 4; i++)
#pragma unroll
                for (int j = 0; j < 4; j++) s[i][j] += a[i] * bb[j];
        }

        // row-wise online softmax update (row spread over 16 lanes)
        float p[4][4], corr[4], rsum[4];
#pragma unroll
        for (int i = 0; i < 4; i++) {
            float tmax = fmaxf(fmaxf(s[i][0], s[i][1]), fmaxf(s[i][2], s[i][3]));
#pragma unroll
            for (int off = 1; off < 16; off <<= 1)
                tmax = fmaxf(tmax, __shfl_xor_sync(0xffffffffu, tmax, off));
            float mnew = fmaxf(mrow[i], tmax);
            corr[i] = __expf(mrow[i] - mnew);
            mrow[i] = mnew;
            float rs = 0.f;
#pragma unroll
            for (int j = 0; j < 4; j++) { p[i][j] = __expf(s[i][j] - mnew); rs += p[i][j]; }
            rsum[i] = rs;
        }
#pragma unroll
        for (int i = 0; i < 4; i++) {
#pragma unroll
            for (int off = 1; off < 16; off <<= 1)
                rsum[i] += __shfl_xor_sync(0xffffffffu, rsum[i], off);
            lrow[i] = lrow[i] * corr[i] + rsum[i];
#pragma unroll
            for (int j = 0; j < 4; j++) acc[i][j] *= corr[i];
        }

        __syncthreads();   // done reading KPs as K
#pragma unroll
        for (int i = 0; i < 4; i++)
#pragma unroll
            for (int j = 0; j < 4; j++)
                KPs[(tx*4 + j)*QS_STRIDE + ty*4 + i] = p[i][j];   // P[k][q]
        __syncthreads();

        // acc += P @ V
#pragma unroll 8
        for (int kk = 0; kk < 64; kk++) {
            float a[4], bb[4];
#pragma unroll
            for (int i = 0; i < 4; i++) a[i]  = KPs[kk*QS_STRIDE + ty*4 + i];
#pragma unroll
            for (int j = 0; j < 4; j++) bb[j] = Vs [kk*VS_STRIDE + tx*4 + j];
#pragma unroll
            for (int i = 0; i < 4; i++)
#pragma unroll
                for (int j = 0; j < 4; j++) acc[i][j] += a[i] * bb[j];
        }
    }

#pragma unroll
    for (int i = 0; i < 4; i++) {
        float inv = 1.f / lrow[i];
        float4 o;
        o.x = acc[i][0]*inv; o.y = acc[i][1]*inv;
        o.z = acc[i][2]*inv; o.w = acc[i][3]*inv;
        *(float4*)(O + (size_t)(s0 + ty*4 + i)*ROWB + base + tx*4) = o;
    }
}

// =================================================================
// LayerNorm over last dim (1024), one block per row
// =================================================================
__global__ __launch_bounds__(256)
void ln_kernel(const float* __restrict__ X, const float* __restrict__ gamma,
               const float* __restrict__ beta, float* __restrict__ out)
{
    const int row = blockIdx.x;
    const int t = threadIdx.x;
    const float* x = X + (size_t)row * HID;

    float4 v = *(const float4*)(x + t*4);
    float s  = v.x + v.y + v.z + v.w;
    float sq = v.x*v.x + v.y*v.y + v.z*v.z + v.w*v.w;
#pragma unroll
    for (int off = 16; off; off >>= 1) {
        s  += __shfl_xor_sync(0xffffffffu, s,  off);
        sq += __shfl_xor_sync(0xffffffffu, sq, off);
    }
    __shared__ float ss[8], sqs[8];
    const int lane = t & 31, wid = t >> 5;
    if (lane == 0) { ss[wid] = s; sqs[wid] = sq; }
    __syncthreads();
    float tot = 0.f, totq = 0.f;
#pragma unroll
    for (int i = 0; i < 8; i++) { tot += ss[i]; totq += sqs[i]; }
    const float mean = tot * (1.f/1024.f);
    const float var  = totq * (1.f/1024.f) - mean*mean;
    const float rstd = rsqrtf(var + 1e-12f);

    float4 g = *(const float4*)(gamma + t*4);
    float4 bb = *(const float4*)(beta + t*4);
    float4 o;
    o.x = (v.x - mean)*rstd*g.x + bb.x;
    o.y = (v.y - mean)*rstd*g.y + bb.y;
    o.z = (v.z - mean)*rstd*g.z + bb.z;
    o.w = (v.w - mean)*rstd*g.w + bb.w;
    *(float4*)(out + (size_t)row*HID + t*4) = o;
}

// =================================================================
extern "C" void kernel_launch(void* const* d_in, const int* in_sizes, int n_in,
                              void* d_out, int out_size)
{
    const float* input = (const float*)d_in[0];
    const float* mask  = (const float*)d_in[1];
    const float* Wq = (const float*)d_in[2];
    const float* bq = (const float*)d_in[3];
    const float* Wk = (const float*)d_in[4];
    const float* bk = (const float*)d_in[5];
    const float* Wv = (const float*)d_in[6];
    const float* bv = (const float*)d_in[7];
    const float* Wo = (const float*)d_in[8];
    const float* bo = (const float*)d_in[9];
    const float* gamma = (const float*)d_in[10];
    const float* beta  = (const float*)d_in[11];

    float *x, *q, *k, *v, *ctx, *y;
    cudaGetSymbolAddress((void**)&x,   g_x);
    cudaGetSymbolAddress((void**)&q,   g_q);
    cudaGetSymbolAddress((void**)&k,   g_k);
    cudaGetSymbolAddress((void**)&v,   g_v);
    cudaGetSymbolAddress((void**)&ctx, g_ctx);
    cudaGetSymbolAddress((void**)&y,   g_y);

    cudaFuncSetAttribute(attn_kernel, cudaFuncAttributeMaxDynamicSharedMemorySize, ATTN_SMEM);

    cudaMemcpyAsync(x, input, sizeof(float)*(size_t)M_ROWS*HID,
                    cudaMemcpyDeviceToDevice, 0);

    for (int l = 0; l < NLAYER; l++) {
        const size_t woff = (size_t)l * HID * HID;
        const size_t voff = (size_t)l * HID;

        qkv_gemm_kernel<<<dim3(8, 32, 3), 256>>>(
            x, Wq + woff, Wk + woff, Wv + woff,
            bq + voff, bk + voff, bv + voff, q, k, v);

        attn_kernel<<<dim3(S_LEN/64, BATCH*NHEAD), 256, ATTN_SMEM>>>(q, k, v, mask, ctx);

        sgemm_kernel<<<dim3(8, 32), 256>>>(ctx, Wo + woff, bo + voff, x, y);

        float* dst = (l == NLAYER - 1) ? (float*)d_out : x;
        ln_kernel<<<M_ROWS, 256>>>(y, gamma + voff, beta + voff, dst);
    }
}

// round 2
// speedup vs baseline: 2.1303x; 2.1303x over previous
#include <cuda_runtime.h>
#include <cuda_bf16.h>
#include <cstdint>

#define S_LEN  2048
#define BATCH  2
#define HID    1024
#define NHEAD  16
#define HDIM   64
#define NLAYER 12
#define M_ROWS (S_LEN*BATCH)   // 4096
#define ROWB   (BATCH*HID)     // 2048
#define NELEM  (M_ROWS*HID)    // 4194304
#define WELEM  (NLAYER*HID*HID) // per weight tensor: 12M

typedef __nv_bfloat16 bf16;

// ---------------- scratch ----------------
__device__ float g_x [NELEM];
__device__ float g_y [NELEM];
__device__ bf16  g_xh[NELEM], g_xl[NELEM];
__device__ bf16  g_qh[NELEM], g_ql[NELEM];
__device__ bf16  g_kh[NELEM], g_kl[NELEM];
__device__ bf16  g_vh[NELEM], g_vl[NELEM];
__device__ bf16  g_ch[NELEM], g_cl[NELEM];
__device__ bf16  g_wh[4ull*WELEM], g_wl[4ull*WELEM];

// ---------------- helpers ----------------
__device__ __forceinline__ uint32_t smem_u32(const void* p) {
    return (uint32_t)__cvta_generic_to_shared(p);
}
__device__ __forceinline__ void ldsm4(uint32_t a, uint32_t& r0, uint32_t& r1, uint32_t& r2, uint32_t& r3) {
    asm volatile("ldmatrix.sync.aligned.m8n8.x4.shared.b16 {%0,%1,%2,%3},[%4];"
        : "=r"(r0), "=r"(r1), "=r"(r2), "=r"(r3) : "r"(a));
}
__device__ __forceinline__ void ldsm4t(uint32_t a, uint32_t& r0, uint32_t& r1, uint32_t& r2, uint32_t& r3) {
    asm volatile("ldmatrix.sync.aligned.m8n8.x4.trans.shared.b16 {%0,%1,%2,%3},[%4];"
        : "=r"(r0), "=r"(r1), "=r"(r2), "=r"(r3) : "r"(a));
}
__device__ __forceinline__ void mma16816(float* c, uint32_t a0, uint32_t a1, uint32_t a2, uint32_t a3,
                                         uint32_t b0, uint32_t b1) {
    asm volatile("mma.sync.aligned.m16n8k16.row.col.f32.bf16.bf16.f32 "
        "{%0,%1,%2,%3},{%4,%5,%6,%7},{%8,%9},{%0,%1,%2,%3};"
        : "+f"(c[0]), "+f"(c[1]), "+f"(c[2]), "+f"(c[3])
        : "r"(a0), "r"(a1), "r"(a2), "r"(a3), "r"(b0), "r"(b1));
}
__device__ __forceinline__ uint32_t pack2(bf16 x, bf16 y) {
    __nv_bfloat162 p = __halves2bfloat162(x, y);
    return *reinterpret_cast<uint32_t*>(&p);
}
__device__ __forceinline__ void pack_hl2(float x, float y, uint32_t& hi, uint32_t& lo) {
    bf16 hx = __float2bfloat16(x), hy = __float2bfloat16(y);
    bf16 lx = __float2bfloat16(x - __bfloat162float(hx));
    bf16 ly = __float2bfloat16(y - __bfloat162float(hy));
    hi = pack2(hx, hy); lo = pack2(lx, ly);
}

// =================================================================
// bf16x3 GEMM core: C[4096x1024] = A[4096x1024] @ W[1024x1024]
// block 128x128, 256 thr = 8 warps (2m x 4n), warp 64x32, KT=32
// A smem [m][k] stride 56; W smem [k][n] stride 136 (trans ldsm)
// =================================================================
#define ASTR 56
#define BSTR 136

__device__ __forceinline__ void gemm_core_bf3(
    const bf16* __restrict__ Ah, const bf16* __restrict__ Al,
    const bf16* __restrict__ Wh, const bf16* __restrict__ Wl,
    float acc[4][4][4])
{
    __shared__ bf16 sA[2][128][ASTR];
    __shared__ bf16 sB[2][32][BSTR];

    const int t = threadIdx.x;
    const int L = t & 31, w = t >> 5;
    const int wm = (w >> 2) * 64, wn = (w & 3) * 32;
    const int m0 = blockIdx.y * 128, n0 = blockIdx.x * 128;

    const int ar = t >> 1, ac = (t & 1) * 16;
    const int br = t >> 3, bc = (t & 7) * 16;

#pragma unroll
    for (int i = 0; i < 4; i++)
#pragma unroll
        for (int j = 0; j < 4; j++)
#pragma unroll
            for (int r = 0; r < 4; r++) acc[i][j][r] = 0.f;

    for (int k0 = 0; k0 < HID; k0 += 32) {
        {
            const size_t ga = (size_t)(m0 + ar) * HID + k0 + ac;
            const uint4* pAh = (const uint4*)(Ah + ga);
            const uint4* pAl = (const uint4*)(Al + ga);
            *(uint4*)&sA[0][ar][ac]     = pAh[0];
            *(uint4*)&sA[0][ar][ac + 8] = pAh[1];
            *(uint4*)&sA[1][ar][ac]     = pAl[0];
            *(uint4*)&sA[1][ar][ac + 8] = pAl[1];
            const size_t gb = (size_t)(k0 + br) * HID + n0 + bc;
            const uint4* pBh = (const uint4*)(Wh + gb);
            const uint4* pBl = (const uint4*)(Wl + gb);
            *(uint4*)&sB[0][br][bc]     = pBh[0];
            *(uint4*)&sB[0][br][bc + 8] = pBh[1];
            *(uint4*)&sB[1][br][bc]     = pBl[0];
            *(uint4*)&sB[1][br][bc + 8] = pBl[1];
        }
        __syncthreads();
#pragma unroll
        for (int ks = 0; ks < 2; ks++) {
            const int kk = ks * 16;
            uint32_t bh[2][4], bl[2][4];
#pragma unroll
            for (int nh = 0; nh < 2; nh++) {
                const int brow = kk + (L & 15);
                const int bcol = wn + nh * 16 + ((L >> 4) << 3);
                ldsm4t(smem_u32(&sB[0][brow][bcol]), bh[nh][0], bh[nh][1], bh[nh][2], bh[nh][3]);
                ldsm4t(smem_u32(&sB[1][brow][bcol]), bl[nh][0], bl[nh][1], bl[nh][2], bl[nh][3]);
            }
#pragma unroll
            for (int mf = 0; mf < 4; mf++) {
                const int arow = wm + mf * 16 + (L & 15);
                const int acol = kk + ((L >> 4) << 3);
                uint32_t a0, a1, a2, a3, e0, e1, e2, e3;
                ldsm4(smem_u32(&sA[0][arow][acol]), a0, a1, a2, a3);
                ldsm4(smem_u32(&sA[1][arow][acol]), e0, e1, e2, e3);
#pragma unroll
                for (int nf = 0; nf < 4; nf++) {
                    uint32_t b0h = bh[nf >> 1][(nf & 1) * 2], b1h = bh[nf >> 1][(nf & 1) * 2 + 1];
                    uint32_t b0l = bl[nf >> 1][(nf & 1) * 2], b1l = bl[nf >> 1][(nf & 1) * 2 + 1];
                    mma16816(acc[mf][nf], a0, a1, a2, a3, b0h, b1h);
                    mma16816(acc[mf][nf], a0, a1, a2, a3, b0l, b1l);
                    mma16816(acc[mf][nf], e0, e1, e2, e3, b0h, b1h);
                }
            }
        }
        __syncthreads();
    }
}

__global__ __launch_bounds__(256)
void qkv_kernel(const bf16* __restrict__ xh, const bf16* __restrict__ xl,
                const bf16* __restrict__ wqh, const bf16* __restrict__ wql,
                const bf16* __restrict__ wkh, const bf16* __restrict__ wkl,
                const bf16* __restrict__ wvh, const bf16* __restrict__ wvl,
                const float* __restrict__ bq, const float* __restrict__ bk, const float* __restrict__ bv,
                bf16* __restrict__ qh, bf16* __restrict__ ql,
                bf16* __restrict__ kh, bf16* __restrict__ kl,
                bf16* __restrict__ vh, bf16* __restrict__ vl)
{
    const bf16 *wh, *wl; const float* bias; bf16 *oh, *ol;
    if (blockIdx.z == 0)      { wh = wqh; wl = wql; bias = bq; oh = qh; ol = ql; }
    else if (blockIdx.z == 1) { wh = wkh; wl = wkl; bias = bk; oh = kh; ol = kl; }
    else                      { wh = wvh; wl = wvl; bias = bv; oh = vh; ol = vl; }

    float acc[4][4][4];
    gemm_core_bf3(xh, xl, wh, wl, acc);

    const int t = threadIdx.x, L = t & 31, w = t >> 5;
    const int wm = (w >> 2) * 64, wn = (w & 3) * 32;
    const int m0 = blockIdx.y * 128, n0 = blockIdx.x * 128;
#pragma unroll
    for (int mf = 0; mf < 4; mf++) {
        const int r0 = m0 + wm + mf * 16 + (L >> 2);
#pragma unroll
        for (int nf = 0; nf < 4; nf++) {
            const int c = n0 + wn + nf * 8 + 2 * (L & 3);
            const float b0 = bias[c], b1 = bias[c + 1];
            uint32_t h, l;
            pack_hl2(acc[mf][nf][0] + b0, acc[mf][nf][1] + b1, h, l);
            *(uint32_t*)&oh[(size_t)r0 * HID + c] = h;
            *(uint32_t*)&ol[(size_t)r0 * HID + c] = l;
            pack_hl2(acc[mf][nf][2] + b0, acc[mf][nf][3] + b1, h, l);
            *(uint32_t*)&oh[(size_t)(r0 + 8) * HID + c] = h;
            *(uint32_t*)&ol[(size_t)(r0 + 8) * HID + c] = l;
        }
    }
}

__global__ __launch_bounds__(256)
void oproj_kernel(const bf16* __restrict__ ch_, const bf16* __restrict__ cl_,
                  const bf16* __restrict__ wh, const bf16* __restrict__ wl,
                  const float* __restrict__ bias, const float* __restrict__ res,
                  float* __restrict__ y)
{
    float acc[4][4][4];
    gemm_core_bf3(ch_, cl_, wh, wl, acc);

    const int t = threadIdx.x, L = t & 31, w = t >> 5;
    const int wm = (w >> 2) * 64, wn = (w & 3) * 32;
    const int m0 = blockIdx.y * 128, n0 = blockIdx.x * 128;
#pragma unroll
    for (int mf = 0; mf < 4; mf++) {
        const int r0 = m0 + wm + mf * 16 + (L >> 2);
#pragma unroll
        for (int nf = 0; nf < 4; nf++) {
            const int c = n0 + wn + nf * 8 + 2 * (L & 3);
            const float b0 = bias[c], b1 = bias[c + 1];
            float2 rv0 = *(const float2*)&res[(size_t)r0 * HID + c];
            float2 rv1 = *(const float2*)&res[(size_t)(r0 + 8) * HID + c];
            float2 o0 = { acc[mf][nf][0] + b0 + rv0.x, acc[mf][nf][1] + b1 + rv0.y };
            float2 o1 = { acc[mf][nf][2] + b0 + rv1.x, acc[mf][nf][3] + b1 + rv1.y };
            *(float2*)&y[(size_t)r0 * HID + c]       = o0;
            *(float2*)&y[(size_t)(r0 + 8) * HID + c] = o1;
        }
    }
}

// =================================================================
// Flash attention, bf16x3 mma. 128 thr = 4 warps; Q tile 64 (16/warp),
// K tile 64, HD=64. smem: Q/K/V hi+lo, [64][72] each.
// =================================================================
#define TSTR 72
#define TBUF (64*TSTR)
#define ATTN_SMEM (6*TBUF*(int)sizeof(bf16))  // 55296

__global__ __launch_bounds__(128)
void attn_bf16(const bf16* __restrict__ qh, const bf16* __restrict__ ql,
               const bf16* __restrict__ kh, const bf16* __restrict__ kl,
               const bf16* __restrict__ vh, const bf16* __restrict__ vl,
               const float* __restrict__ mask,
               bf16* __restrict__ ch_, bf16* __restrict__ cl_)
{
    extern __shared__ bf16 smx[];
    bf16* sQh = smx;            bf16* sQl = smx + TBUF;
    bf16* sKh = smx + 2*TBUF;   bf16* sKl = smx + 3*TBUF;
    bf16* sVh = smx + 4*TBUF;   bf16* sVl = smx + 5*TBUF;

    const int t = threadIdx.x, L = t & 31, w = t >> 5;
    const int s0 = blockIdx.x * 64;
    const int b  = blockIdx.y >> 4, h = blockIdx.y & 15;
    const int base = b * HID + h * HDIM;

    // load Q tile
    {
        const int row = t >> 1, cc = (t & 1) * 32;
        const size_t g = (size_t)(s0 + row) * ROWB + base + cc;
#pragma unroll
        for (int c = 0; c < 4; c++) {
            *(uint4*)&sQh[row * TSTR + cc + c * 8] = *(const uint4*)(qh + g + c * 8);
            *(uint4*)&sQl[row * TSTR + cc + c * 8] = *(const uint4*)(ql + g + c * 8);
        }
    }
    __syncthreads();

    uint32_t qf[2][4][4];
#pragma unroll
    for (int ks = 0; ks < 4; ks++) {
        const int qrow = w * 16 + (L & 15);
        const int qcol = ks * 16 + ((L >> 4) << 3);
        ldsm4(smem_u32(&sQh[qrow * TSTR + qcol]), qf[0][ks][0], qf[0][ks][1], qf[0][ks][2], qf[0][ks][3]);
        ldsm4(smem_u32(&sQl[qrow * TSTR + qcol]), qf[1][ks][0], qf[1][ks][1], qf[1][ks][2], qf[1][ks][3]);
    }

    float oacc[8][4];
#pragma unroll
    for (int i = 0; i < 8; i++)
#pragma unroll
        for (int j = 0; j < 4; j++) oacc[i][j] = 0.f;
    float mrow0 = -1e30f, mrow1 = -1e30f, lrow0 = 0.f, lrow1 = 0.f;

    for (int kt = 0; kt < S_LEN / 64; kt++) {
        __syncthreads();
        {
            const int row = t >> 1, cc = (t & 1) * 32;
            const size_t g = (size_t)(kt * 64 + row) * ROWB + base + cc;
#pragma unroll
            for (int c = 0; c < 4; c++) {
                *(uint4*)&sKh[row * TSTR + cc + c * 8] = *(const uint4*)(kh + g + c * 8);
                *(uint4*)&sKl[row * TSTR + cc + c * 8] = *(const uint4*)(kl + g + c * 8);
                *(uint4*)&sVh[row * TSTR + cc + c * 8] = *(const uint4*)(vh + g + c * 8);
                *(uint4*)&sVl[row * TSTR + cc + c * 8] = *(const uint4*)(vl + g + c * 8);
            }
        }
        __syncthreads();

        float sc[8][4];
#pragma unroll
        for (int i = 0; i < 8; i++)
#pragma unroll
            for (int j = 0; j < 4; j++) sc[i][j] = 0.f;

#pragma unroll
        for (int ks = 0; ks < 4; ks++) {
            uint32_t kbh[4][4], kbl[4][4];
#pragma unroll
            for (int nh = 0; nh < 4; nh++) {
                const int krow = nh * 16 + (L & 7) + ((L >> 4) << 3);
                const int kcol = ks * 16 + (((L >> 3) & 1) << 3);
                ldsm4(smem_u32(&sKh[krow * TSTR + kcol]), kbh[nh][0], kbh[nh][1], kbh[nh][2], kbh[nh][3]);
                ldsm4(smem_u32(&sKl[krow * TSTR + kcol]), kbl[nh][0], kbl[nh][1], kbl[nh][2], kbl[nh][3]);
            }
#pragma unroll
            for (int nf = 0; nf < 8; nf++) {
                uint32_t b0h = kbh[nf >> 1][(nf & 1) * 2], b1h = kbh[nf >> 1][(nf & 1) * 2 + 1];
                uint32_t b0l = kbl[nf >> 1][(nf & 1) * 2], b1l = kbl[nf >> 1][(nf & 1) * 2 + 1];
                mma16816(sc[nf], qf[0][ks][0], qf[0][ks][1], qf[0][ks][2], qf[0][ks][3], b0h, b1h);
                mma16816(sc[nf], qf[0][ks][0], qf[0][ks][1], qf[0][ks][2], qf[0][ks][3], b0l, b1l);
                mma16816(sc[nf], qf[1][ks][0], qf[1][ks][1], qf[1][ks][2], qf[1][ks][3], b0h, b1h);
            }
        }

        // scale + mask
        const float* mg = mask + (size_t)b * S_LEN + kt * 64;
#pragma unroll
        for (int nf = 0; nf < 8; nf++) {
            const int c0 = nf * 8 + 2 * (L & 3);
            const float m0v = mg[c0], m1v = mg[c0 + 1];
            sc[nf][0] = sc[nf][0] * 0.125f + m0v;
            sc[nf][1] = sc[nf][1] * 0.125f + m1v;
            sc[nf][2] = sc[nf][2] * 0.125f + m0v;
            sc[nf][3] = sc[nf][3] * 0.125f + m1v;
        }

        // online softmax
        float tm0 = -1e30f, tm1 = -1e30f;
#pragma unroll
        for (int nf = 0; nf < 8; nf++) {
            tm0 = fmaxf(tm0, fmaxf(sc[nf][0], sc[nf][1]));
            tm1 = fmaxf(tm1, fmaxf(sc[nf][2], sc[nf][3]));
        }
        tm0 = fmaxf(tm0, __shfl_xor_sync(0xffffffffu, tm0, 1));
        tm0 = fmaxf(tm0, __shfl_xor_sync(0xffffffffu, tm0, 2));
        tm1 = fmaxf(tm1, __shfl_xor_sync(0xffffffffu, tm1, 1));
        tm1 = fmaxf(tm1, __shfl_xor_sync(0xffffffffu, tm1, 2));
        const float mn0 = fmaxf(mrow0, tm0), mn1 = fmaxf(mrow1, tm1);
        const float cr0 = __expf(mrow0 - mn0), cr1 = __expf(mrow1 - mn1);
        mrow0 = mn0; mrow1 = mn1;
        float rs0 = 0.f, rs1 = 0.f;
#pragma unroll
        for (int nf = 0; nf < 8; nf++) {
            sc[nf][0] = __expf(sc[nf][0] - mn0); rs0 += sc[nf][0];
            sc[nf][1] = __expf(sc[nf][1] - mn0); rs0 += sc[nf][1];
            sc[nf][2] = __expf(sc[nf][2] - mn1); rs1 += sc[nf][2];
            sc[nf][3] = __expf(sc[nf][3] - mn1); rs1 += sc[nf][3];
        }
        rs0 += __shfl_xor_sync(0xffffffffu, rs0, 1);
        rs0 += __shfl_xor_sync(0xffffffffu, rs0, 2);
        rs1 += __shfl_xor_sync(0xffffffffu, rs1, 1);
        rs1 += __shfl_xor_sync(0xffffffffu, rs1, 2);
        lrow0 = lrow0 * cr0 + rs0;
        lrow1 = lrow1 * cr1 + rs1;
#pragma unroll
        for (int df = 0; df < 8; df++) {
            oacc[df][0] *= cr0; oacc[df][1] *= cr0;
            oacc[df][2] *= cr1; oacc[df][3] *= cr1;
        }

        // P @ V
#pragma unroll
        for (int ks = 0; ks < 4; ks++) {
            uint32_t ah0, ah1, ah2, ah3, al0, al1, al2, al3;
            pack_hl2(sc[2*ks][0],   sc[2*ks][1],   ah0, al0);
            pack_hl2(sc[2*ks][2],   sc[2*ks][3],   ah1, al1);
            pack_hl2(sc[2*ks+1][0], sc[2*ks+1][1], ah2, al2);
            pack_hl2(sc[2*ks+1][2], sc[2*ks+1][3], ah3, al3);
            uint32_t vbh[4][4], vbl[4][4];
#pragma unroll
            for (int dh = 0; dh < 4; dh++) {
                const int vrow = ks * 16 + (L & 15);
                const int vcol = dh * 16 + ((L >> 4) << 3);
                ldsm4t(smem_u32(&sVh[vrow * TSTR + vcol]), vbh[dh][0], vbh[dh][1], vbh[dh][2], vbh[dh][3]);
                ldsm4t(smem_u32(&sVl[vrow * TSTR + vcol]), vbl[dh][0], vbl[dh][1], vbl[dh][2], vbl[dh][3]);
            }
#pragma unroll
            for (int df = 0; df < 8; df++) {
                uint32_t b0h = vbh[df >> 1][(df & 1) * 2], b1h = vbh[df >> 1][(df & 1) * 2 + 1];
                uint32_t b0l = vbl[df >> 1][(df & 1) * 2], b1l = vbl[df >> 1][(df & 1) * 2 + 1];
                mma16816(oacc[df], ah0, ah1, ah2, ah3, b0h, b1h);
                mma16816(oacc[df], ah0, ah1, ah2, ah3, b0l, b1l);
                mma16816(oacc[df], al0, al1, al2, al3, b0h, b1h);
            }
        }
    }

    const float inv0 = 1.f / lrow0, inv1 = 1.f / lrow1;
    const int r0 = s0 + w * 16 + (L >> 2);
#pragma unroll
    for (int df = 0; df < 8; df++) {
        const int d = df * 8 + 2 * (L & 3);
        const size_t i0 = (size_t)r0 * ROWB + base + d;
        const size_t i1 = i0 + 8 * ROWB;
        uint32_t hh, ll;
        pack_hl2(oacc[df][0] * inv0, oacc[df][1] * inv0, hh, ll);
        *(uint32_t*)&ch_[i0] = hh; *(uint32_t*)&cl_[i0] = ll;
        pack_hl2(oacc[df][2] * inv1, oacc[df][3] * inv1, hh, ll);
        *(uint32_t*)&ch_[i1] = hh; *(uint32_t*)&cl_[i1] = ll;
    }
}

// =================================================================
// LayerNorm; also emits bf16 hi/lo of the output
// =================================================================
__global__ __launch_bounds__(256)
void ln_kernel(const float* __restrict__ X, const float* __restrict__ gamma,
               const float* __restrict__ beta, float* __restrict__ out,
               bf16* __restrict__ oh, bf16* __restrict__ ol)
{
    const int row = blockIdx.x;
    const int t = threadIdx.x;
    const float* x = X + (size_t)row * HID;

    float4 v = *(const float4*)(x + t * 4);
    float s  = v.x + v.y + v.z + v.w;
    float sq = v.x*v.x + v.y*v.y + v.z*v.z + v.w*v.w;
#pragma unroll
    for (int off = 16; off; off >>= 1) {
        s  += __shfl_xor_sync(0xffffffffu, s,  off);
        sq += __shfl_xor_sync(0xffffffffu, sq, off);
    }
    __shared__ float ss[8], sqs[8];
    const int lane = t & 31, wid = t >> 5;
    if (lane == 0) { ss[wid] = s; sqs[wid] = sq; }
    __syncthreads();
    float tot = 0.f, totq = 0.f;
#pragma unroll
    for (int i = 0; i < 8; i++) { tot += ss[i]; totq += sqs[i]; }
    const float mean = tot * (1.f/1024.f);
    const float var  = totq * (1.f/1024.f) - mean * mean;
    const float rstd = rsqrtf(var + 1e-12f);

    float4 g  = *(const float4*)(gamma + t * 4);
    float4 bb = *(const float4*)(beta + t * 4);
    float4 o;
    o.x = (v.x - mean) * rstd * g.x + bb.x;
    o.y = (v.y - mean) * rstd * g.y + bb.y;
    o.z = (v.z - mean) * rstd * g.z + bb.z;
    o.w = (v.w - mean) * rstd * g.w + bb.w;
    *(float4*)(out + (size_t)row * HID + t * 4) = o;

    uint32_t h0, l0, h1, l1;
    pack_hl2(o.x, o.y, h0, l0);
    pack_hl2(o.z, o.w, h1, l1);
    const size_t idx = (size_t)row * HID + t * 4;
    *(uint32_t*)&oh[idx]     = h0; *(uint32_t*)&ol[idx]     = l0;
    *(uint32_t*)&oh[idx + 2] = h1; *(uint32_t*)&ol[idx + 2] = l1;
}

// ---------------- conversion kernels ----------------
__global__ void wconv_kernel(const float* __restrict__ w0, const float* __restrict__ w1,
                             const float* __restrict__ w2, const float* __restrict__ w3,
                             bf16* __restrict__ wh, bf16* __restrict__ wl)
{
    const float* src;
    const int m = blockIdx.y;
    if (m == 0) src = w0; else if (m == 1) src = w1; else if (m == 2) src = w2; else src = w3;
    const size_t off = (size_t)m * WELEM;
    for (size_t i = (size_t)blockIdx.x * blockDim.x + threadIdx.x; i < (size_t)WELEM;
         i += (size_t)gridDim.x * blockDim.x) {
        float v = src[i];
        bf16 h = __float2bfloat16(v);
        wh[off + i] = h;
        wl[off + i] = __float2bfloat16(v - __bfloat162float(h));
    }
}

__global__ void xconv_kernel(const float* __restrict__ in, float* __restrict__ xo,
                             bf16* __restrict__ xh, bf16* __restrict__ xl)
{
    for (size_t i = (size_t)blockIdx.x * blockDim.x + threadIdx.x; i < (size_t)NELEM;
         i += (size_t)gridDim.x * blockDim.x) {
        float v = in[i];
        xo[i] = v;
        bf16 h = __float2bfloat16(v);
        xh[i] = h;
        xl[i] = __float2bfloat16(v - __bfloat162float(h));
    }
}

// =================================================================
extern "C" void kernel_launch(void* const* d_in, const int* in_sizes, int n_in,
                              void* d_out, int out_size)
{
    const float* input = (const float*)d_in[0];
    const float* mask  = (const float*)d_in[1];
    const float* Wq = (const float*)d_in[2];
    const float* bq = (const float*)d_in[3];
    const float* Wk = (const float*)d_in[4];
    const float* bk = (const float*)d_in[5];
    const float* Wv = (const float*)d_in[6];
    const float* bv = (const float*)d_in[7];
    const float* Wo = (const float*)d_in[8];
    const float* bo = (const float*)d_in[9];
    const float* gamma = (const float*)d_in[10];
    const float* beta  = (const float*)d_in[11];

    float *x, *y; bf16 *xh, *xl, *qh, *ql, *kh, *kl, *vh, *vl, *ch, *cl, *wh, *wl;
    cudaGetSymbolAddress((void**)&x,  g_x);  cudaGetSymbolAddress((void**)&y,  g_y);
    cudaGetSymbolAddress((void**)&xh, g_xh); cudaGetSymbolAddress((void**)&xl, g_xl);
    cudaGetSymbolAddress((void**)&qh, g_qh); cudaGetSymbolAddress((void**)&ql, g_ql);
    cudaGetSymbolAddress((void**)&kh, g_kh); cudaGetSymbolAddress((void**)&kl, g_kl);
    cudaGetSymbolAddress((void**)&vh, g_vh); cudaGetSymbolAddress((void**)&vl, g_vl);
    cudaGetSymbolAddress((void**)&ch, g_ch); cudaGetSymbolAddress((void**)&cl, g_cl);
    cudaGetSymbolAddress((void**)&wh, g_wh); cudaGetSymbolAddress((void**)&wl, g_wl);

    cudaFuncSetAttribute(attn_bf16, cudaFuncAttributeMaxDynamicSharedMemorySize, ATTN_SMEM);

    wconv_kernel<<<dim3(4096, 4), 256>>>(Wq, Wk, Wv, Wo, wh, wl);
    xconv_kernel<<<4096, 256>>>(input, x, xh, xl);

    for (int l = 0; l < NLAYER; l++) {
        const size_t wq_o = (size_t)(0 * NLAYER + l) * HID * HID;
        const size_t wk_o = (size_t)(1 * NLAYER + l) * HID * HID;
        const size_t wv_o = (size_t)(2 * NLAYER + l) * HID * HID;
        const size_t wo_o = (size_t)(3 * NLAYER + l) * HID * HID;
        const size_t voff = (size_t)l * HID;

        qkv_kernel<<<dim3(8, 32, 3), 256>>>(
            xh, xl,
            wh + wq_o, wl + wq_o, wh + wk_o, wl + wk_o, wh + wv_o, wl + wv_o,
            bq + voff, bk + voff, bv + voff,
            qh, ql, kh, kl, vh, vl);

        attn_bf16<<<dim3(S_LEN / 64, BATCH * NHEAD), 128, ATTN_SMEM>>>(
            qh, ql, kh, kl, vh, vl, mask, ch, cl);

        oproj_kernel<<<dim3(8, 32), 256>>>(ch, cl, wh + wo_o, wl + wo_o,
                                           bo + voff, x, y);

        float* dst = (l == NLAYER - 1) ? (float*)d_out : x;
        ln_kernel<<<M_ROWS, 256>>>(y, gamma + voff, beta + voff, dst, xh, xl);
        if (l != NLAYER - 1)
            cudaMemcpyAsync(x, dst, 0, cudaMemcpyDeviceToDevice, 0); // no-op keep x==dst
    }
}

// round 3
// speedup vs baseline: 2.4163x; 1.1342x over previous
#include <cuda_runtime.h>
#include <cuda_bf16.h>
#include <cstdint>

#define S_LEN  2048
#define BATCH  2
#define HID    1024
#define NHEAD  16
#define HDIM   64
#define NLAYER 12
#define M_ROWS (S_LEN*BATCH)   // 4096
#define ROWB   (BATCH*HID)     // 2048
#define NELEM  (M_ROWS*HID)
#define WELEM  (NLAYER*HID*HID)

typedef __nv_bfloat16 bf16;

// ---------------- scratch ----------------
__device__ float g_x [NELEM];
__device__ float g_y [NELEM];
__device__ bf16  g_xh[NELEM], g_xl[NELEM];
__device__ bf16  g_qh[NELEM], g_ql[NELEM];
__device__ bf16  g_kh[NELEM], g_kl[NELEM];
__device__ bf16  g_vh[NELEM], g_vl[NELEM];
__device__ bf16  g_ch[NELEM], g_cl[NELEM];
__device__ bf16  g_wh[4ull*WELEM], g_wl[4ull*WELEM];

// ---------------- helpers ----------------
__device__ __forceinline__ uint32_t smem_u32(const void* p) {
    return (uint32_t)__cvta_generic_to_shared(p);
}
__device__ __forceinline__ void cp16(void* s, const void* g) {
    asm volatile("cp.async.cg.shared.global [%0], [%1], 16;"
        :: "r"(smem_u32(s)), "l"(g));
}
#define CP_COMMIT asm volatile("cp.async.commit_group;")
#define CP_WAIT(N) asm volatile("cp.async.wait_group %0;" :: "n"(N))

__device__ __forceinline__ void ldsm4(uint32_t a, uint32_t& r0, uint32_t& r1, uint32_t& r2, uint32_t& r3) {
    asm volatile("ldmatrix.sync.aligned.m8n8.x4.shared.b16 {%0,%1,%2,%3},[%4];"
        : "=r"(r0), "=r"(r1), "=r"(r2), "=r"(r3) : "r"(a));
}
__device__ __forceinline__ void ldsm4t(uint32_t a, uint32_t& r0, uint32_t& r1, uint32_t& r2, uint32_t& r3) {
    asm volatile("ldmatrix.sync.aligned.m8n8.x4.trans.shared.b16 {%0,%1,%2,%3},[%4];"
        : "=r"(r0), "=r"(r1), "=r"(r2), "=r"(r3) : "r"(a));
}
__device__ __forceinline__ void mma16816(float* c, uint32_t a0, uint32_t a1, uint32_t a2, uint32_t a3,
                                         uint32_t b0, uint32_t b1) {
    asm volatile("mma.sync.aligned.m16n8k16.row.col.f32.bf16.bf16.f32 "
        "{%0,%1,%2,%3},{%4,%5,%6,%7},{%8,%9},{%0,%1,%2,%3};"
        : "+f"(c[0]), "+f"(c[1]), "+f"(c[2]), "+f"(c[3])
        : "r"(a0), "r"(a1), "r"(a2), "r"(a3), "r"(b0), "r"(b1));
}
__device__ __forceinline__ uint32_t pack2(bf16 x, bf16 y) {
    __nv_bfloat162 p = __halves2bfloat162(x, y);
    return *reinterpret_cast<uint32_t*>(&p);
}
__device__ __forceinline__ void pack_hl2(float x, float y, uint32_t& hi, uint32_t& lo) {
    bf16 hx = __float2bfloat16(x), hy = __float2bfloat16(y);
    bf16 lx = __float2bfloat16(x - __bfloat162float(hx));
    bf16 ly = __float2bfloat16(y - __bfloat162float(hy));
    hi = pack2(hx, hy); lo = pack2(lx, ly);
}

// =================================================================
// bf16x3 GEMM, cp.async double-buffered.
// block 128x128, 256 thr = 8 warps (2m x 4n), warp 64x32, KT=32
// =================================================================
#define ASTR 56
#define BSTR 136
#define SA_OFF(st,hl) (((st)*2+(hl))*128*ASTR)
#define SB_BASE (4*128*ASTR)
#define SB_OFF(st,hl) (SB_BASE + ((st)*2+(hl))*32*BSTR)
#define GEMM_SMEM ((4*128*ASTR + 4*32*BSTR)*(int)sizeof(bf16))  // 92160

__device__ __forceinline__ void gemm_issue(
    bf16* dsm, const bf16* __restrict__ Ah, const bf16* __restrict__ Al,
    const bf16* __restrict__ Wh, const bf16* __restrict__ Wl,
    int m0, int n0, int k0, int st, int t)
{
    const int ar = t >> 1, ac = (t & 1) * 16;
    const size_t ga = (size_t)(m0 + ar) * HID + k0 + ac;
    bf16* a0 = dsm + SA_OFF(st, 0) + ar * ASTR + ac;
    bf16* a1 = dsm + SA_OFF(st, 1) + ar * ASTR + ac;
    cp16(a0,     Ah + ga); cp16(a0 + 8, Ah + ga + 8);
    cp16(a1,     Al + ga); cp16(a1 + 8, Al + ga + 8);
    const int br = t >> 3, bc = (t & 7) * 16;
    const size_t gb = (size_t)(k0 + br) * HID + n0 + bc;
    bf16* b0 = dsm + SB_OFF(st, 0) + br * BSTR + bc;
    bf16* b1 = dsm + SB_OFF(st, 1) + br * BSTR + bc;
    cp16(b0,     Wh + gb); cp16(b0 + 8, Wh + gb + 8);
    cp16(b1,     Wl + gb); cp16(b1 + 8, Wl + gb + 8);
}

__device__ __forceinline__ void gemm_core_bf3(
    const bf16* __restrict__ Ah, const bf16* __restrict__ Al,
    const bf16* __restrict__ Wh, const bf16* __restrict__ Wl,
    float acc[4][4][4])
{
    extern __shared__ bf16 dsm[];
    const int t = threadIdx.x;
    const int L = t & 31, w = t >> 5;
    const int wm = (w >> 2) * 64, wn = (w & 3) * 32;
    const int m0 = blockIdx.y * 128, n0 = blockIdx.x * 128;

#pragma unroll
    for (int i = 0; i < 4; i++)
#pragma unroll
        for (int j = 0; j < 4; j++)
#pragma unroll
            for (int r = 0; r < 4; r++) acc[i][j][r] = 0.f;

    gemm_issue(dsm, Ah, Al, Wh, Wl, m0, n0, 0,  0, t); CP_COMMIT;
    gemm_issue(dsm, Ah, Al, Wh, Wl, m0, n0, 32, 1, t); CP_COMMIT;

    for (int ko = 0; ko < HID / 32; ko++) {
        CP_WAIT(1);
        __syncthreads();
        const int st = ko & 1;
        const bf16* cA0 = dsm + SA_OFF(st, 0);
        const bf16* cA1 = dsm + SA_OFF(st, 1);
        const bf16* cB0 = dsm + SB_OFF(st, 0);
        const bf16* cB1 = dsm + SB_OFF(st, 1);
#pragma unroll
        for (int ks = 0; ks < 2; ks++) {
            const int kk = ks * 16;
            uint32_t bh[2][4], bl[2][4];
#pragma unroll
            for (int nh = 0; nh < 2; nh++) {
                const int brow = kk + (L & 15);
                const int bcol = wn + nh * 16 + ((L >> 4) << 3);
                ldsm4t(smem_u32(cB0 + brow * BSTR + bcol), bh[nh][0], bh[nh][1], bh[nh][2], bh[nh][3]);
                ldsm4t(smem_u32(cB1 + brow * BSTR + bcol), bl[nh][0], bl[nh][1], bl[nh][2], bl[nh][3]);
            }
#pragma unroll
            for (int mf = 0; mf < 4; mf++) {
                const int arow = wm + mf * 16 + (L & 15);
                const int acol = kk + ((L >> 4) << 3);
                uint32_t a0, a1, a2, a3, e0, e1, e2, e3;
                ldsm4(smem_u32(cA0 + arow * ASTR + acol), a0, a1, a2, a3);
                ldsm4(smem_u32(cA1 + arow * ASTR + acol), e0, e1, e2, e3);
#pragma unroll
                for (int nf = 0; nf < 4; nf++) {
                    uint32_t b0h = bh[nf >> 1][(nf & 1) * 2], b1h = bh[nf >> 1][(nf & 1) * 2 + 1];
                    uint32_t b0l = bl[nf >> 1][(nf & 1) * 2], b1l = bl[nf >> 1][(nf & 1) * 2 + 1];
                    mma16816(acc[mf][nf], a0, a1, a2, a3, b0h, b1h);
                    mma16816(acc[mf][nf], a0, a1, a2, a3, b0l, b1l);
                    mma16816(acc[mf][nf], e0, e1, e2, e3, b0h, b1h);
                }
            }
        }
        __syncthreads();
        if (ko + 2 < HID / 32)
            gemm_issue(dsm, Ah, Al, Wh, Wl, m0, n0, (ko + 2) * 32, st, t);
        CP_COMMIT;
    }
}

__global__ __launch_bounds__(256)
void qkv_kernel(const bf16* __restrict__ xh, const bf16* __restrict__ xl,
                const bf16* __restrict__ wqh, const bf16* __restrict__ wql,
                const bf16* __restrict__ wkh, const bf16* __restrict__ wkl,
                const bf16* __restrict__ wvh, const bf16* __restrict__ wvl,
                const float* __restrict__ bq, const float* __restrict__ bk, const float* __restrict__ bv,
                bf16* __restrict__ qh, bf16* __restrict__ ql,
                bf16* __restrict__ kh, bf16* __restrict__ kl,
                bf16* __restrict__ vh, bf16* __restrict__ vl)
{
    const bf16 *wh, *wl; const float* bias; bf16 *oh, *ol;
    if (blockIdx.z == 0)      { wh = wqh; wl = wql; bias = bq; oh = qh; ol = ql; }
    else if (blockIdx.z == 1) { wh = wkh; wl = wkl; bias = bk; oh = kh; ol = kl; }
    else                      { wh = wvh; wl = wvl; bias = bv; oh = vh; ol = vl; }

    float acc[4][4][4];
    gemm_core_bf3(xh, xl, wh, wl, acc);

    const int t = threadIdx.x, L = t & 31, w = t >> 5;
    const int wm = (w >> 2) * 64, wn = (w & 3) * 32;
    const int m0 = blockIdx.y * 128, n0 = blockIdx.x * 128;
#pragma unroll
    for (int mf = 0; mf < 4; mf++) {
        const int r0 = m0 + wm + mf * 16 + (L >> 2);
#pragma unroll
        for (int nf = 0; nf < 4; nf++) {
            const int c = n0 + wn + nf * 8 + 2 * (L & 3);
            const float b0 = bias[c], b1 = bias[c + 1];
            uint32_t h, l;
            pack_hl2(acc[mf][nf][0] + b0, acc[mf][nf][1] + b1, h, l);
            *(uint32_t*)&oh[(size_t)r0 * HID + c] = h;
            *(uint32_t*)&ol[(size_t)r0 * HID + c] = l;
            pack_hl2(acc[mf][nf][2] + b0, acc[mf][nf][3] + b1, h, l);
            *(uint32_t*)&oh[(size_t)(r0 + 8) * HID + c] = h;
            *(uint32_t*)&ol[(size_t)(r0 + 8) * HID + c] = l;
        }
    }
}

__global__ __launch_bounds__(256)
void oproj_kernel(const bf16* __restrict__ ch_, const bf16* __restrict__ cl_,
                  const bf16* __restrict__ wh, const bf16* __restrict__ wl,
                  const float* __restrict__ bias, const float* __restrict__ res,
                  float* __restrict__ y)
{
    float acc[4][4][4];
    gemm_core_bf3(ch_, cl_, wh, wl, acc);

    const int t = threadIdx.x, L = t & 31, w = t >> 5;
    const int wm = (w >> 2) * 64, wn = (w & 3) * 32;
    const int m0 = blockIdx.y * 128, n0 = blockIdx.x * 128;
#pragma unroll
    for (int mf = 0; mf < 4; mf++) {
        const int r0 = m0 + wm + mf * 16 + (L >> 2);
#pragma unroll
        for (int nf = 0; nf < 4; nf++) {
            const int c = n0 + wn + nf * 8 + 2 * (L & 3);
            const float b0 = bias[c], b1 = bias[c + 1];
            float2 rv0 = *(const float2*)&res[(size_t)r0 * HID + c];
            float2 rv1 = *(const float2*)&res[(size_t)(r0 + 8) * HID + c];
            float2 o0 = { acc[mf][nf][0] + b0 + rv0.x, acc[mf][nf][1] + b1 + rv0.y };
            float2 o1 = { acc[mf][nf][2] + b0 + rv1.x, acc[mf][nf][3] + b1 + rv1.y };
            *(float2*)&y[(size_t)r0 * HID + c]       = o0;
            *(float2*)&y[(size_t)(r0 + 8) * HID + c] = o1;
        }
    }
}

// =================================================================
// Flash attention bf16x3: 256 thr (8 warps), Q-tile 128 (16/warp),
// K-tile 64, cp.async double-buffered K/V stages.
// =================================================================
#define TSTR 72
#define QT   128
#define AT_QH 0
#define AT_QL (QT*TSTR)
#define AT_ST(st) (2*QT*TSTR + (st)*4*64*TSTR)
#define AT_KL (64*TSTR)
#define AT_VH (2*64*TSTR)
#define AT_VL (3*64*TSTR)
#define ATTN_SMEM ((2*QT*TSTR + 8*64*TSTR)*(int)sizeof(bf16))  // 110592

__device__ __forceinline__ void attn_issue_kv(
    bf16* dsm, const bf16* __restrict__ kh, const bf16* __restrict__ kl,
    const bf16* __restrict__ vh, const bf16* __restrict__ vl,
    int kt, int st, int base, int t)
{
    const int row = t >> 2, c4 = (t & 3) * 16;
    const size_t g = (size_t)(kt * 64 + row) * ROWB + base + c4;
    bf16* s = dsm + AT_ST(st);
    bf16* pk0 = s +          row * TSTR + c4;
    bf16* pk1 = s + AT_KL  + row * TSTR + c4;
    bf16* pv0 = s + AT_VH  + row * TSTR + c4;
    bf16* pv1 = s + AT_VL  + row * TSTR + c4;
    cp16(pk0, kh + g); cp16(pk0 + 8, kh + g + 8);
    cp16(pk1, kl + g); cp16(pk1 + 8, kl + g + 8);
    cp16(pv0, vh + g); cp16(pv0 + 8, vh + g + 8);
    cp16(pv1, vl + g); cp16(pv1 + 8, vl + g + 8);
}

__global__ __launch_bounds__(256)
void attn_bf16(const bf16* __restrict__ qh, const bf16* __restrict__ ql,
               const bf16* __restrict__ kh, const bf16* __restrict__ kl,
               const bf16* __restrict__ vh, const bf16* __restrict__ vl,
               const float* __restrict__ mask,
               bf16* __restrict__ ch_, bf16* __restrict__ cl_)
{
    extern __shared__ bf16 dsm[];
    const int t = threadIdx.x, L = t & 31, w = t >> 5;
    const int s0 = blockIdx.x * QT;
    const int b  = blockIdx.y >> 4, h = blockIdx.y & 15;
    const int base = b * HID + h * HDIM;

    // issue Q (group 0), then KV kt=0,1 (groups 1,2)
    {
        const int row = t >> 1, cc = (t & 1) * 32;
        const size_t g = (size_t)(s0 + row) * ROWB + base + cc;
        bf16* pq0 = dsm + AT_QH + row * TSTR + cc;
        bf16* pq1 = dsm + AT_QL + row * TSTR + cc;
#pragma unroll
        for (int c = 0; c < 4; c++) {
            cp16(pq0 + c * 8, qh + g + c * 8);
            cp16(pq1 + c * 8, ql + g + c * 8);
        }
    }
    CP_COMMIT;
    attn_issue_kv(dsm, kh, kl, vh, vl, 0, 0, base, t); CP_COMMIT;
    attn_issue_kv(dsm, kh, kl, vh, vl, 1, 1, base, t); CP_COMMIT;

    CP_WAIT(2);
    __syncthreads();

    uint32_t qf[2][4][4];
#pragma unroll
    for (int ks = 0; ks < 4; ks++) {
        const int qrow = w * 16 + (L & 15);
        const int qcol = ks * 16 + ((L >> 4) << 3);
        ldsm4(smem_u32(dsm + AT_QH + qrow * TSTR + qcol), qf[0][ks][0], qf[0][ks][1], qf[0][ks][2], qf[0][ks][3]);
        ldsm4(smem_u32(dsm + AT_QL + qrow * TSTR + qcol), qf[1][ks][0], qf[1][ks][1], qf[1][ks][2], qf[1][ks][3]);
    }

    float oacc[8][4];
#pragma unroll
    for (int i = 0; i < 8; i++)
#pragma unroll
        for (int j = 0; j < 4; j++) oacc[i][j] = 0.f;
    float mrow0 = -1e30f, mrow1 = -1e30f, lrow0 = 0.f, lrow1 = 0.f;

    for (int kt = 0; kt < S_LEN / 64; kt++) {
        CP_WAIT(1);
        __syncthreads();
        const bf16* s   = dsm + AT_ST(kt & 1);
        const bf16* sKh = s;
        const bf16* sKl = s + AT_KL;
        const bf16* sVh = s + AT_VH;
        const bf16* sVl = s + AT_VL;

        float sc[8][4];
#pragma unroll
        for (int i = 0; i < 8; i++)
#pragma unroll
            for (int j = 0; j < 4; j++) sc[i][j] = 0.f;

#pragma unroll
        for (int ks = 0; ks < 4; ks++) {
            uint32_t kbh[4][4], kbl[4][4];
#pragma unroll
            for (int nh = 0; nh < 4; nh++) {
                const int krow = nh * 16 + (L & 7) + ((L >> 4) << 3);
                const int kcol = ks * 16 + (((L >> 3) & 1) << 3);
                ldsm4(smem_u32(sKh + krow * TSTR + kcol), kbh[nh][0], kbh[nh][1], kbh[nh][2], kbh[nh][3]);
                ldsm4(smem_u32(sKl + krow * TSTR + kcol), kbl[nh][0], kbl[nh][1], kbl[nh][2], kbl[nh][3]);
            }
#pragma unroll
            for (int nf = 0; nf < 8; nf++) {
                uint32_t b0h = kbh[nf >> 1][(nf & 1) * 2], b1h = kbh[nf >> 1][(nf & 1) * 2 + 1];
                uint32_t b0l = kbl[nf >> 1][(nf & 1) * 2], b1l = kbl[nf >> 1][(nf & 1) * 2 + 1];
                mma16816(sc[nf], qf[0][ks][0], qf[0][ks][1], qf[0][ks][2], qf[0][ks][3], b0h, b1h);
                mma16816(sc[nf], qf[0][ks][0], qf[0][ks][1], qf[0][ks][2], qf[0][ks][3], b0l, b1l);
                mma16816(sc[nf], qf[1][ks][0], qf[1][ks][1], qf[1][ks][2], qf[1][ks][3], b0h, b1h);
            }
        }

        // scale + mask
        const float* mg = mask + (size_t)b * S_LEN + kt * 64;
#pragma unroll
        for (int nf = 0; nf < 8; nf++) {
            const int c0 = nf * 8 + 2 * (L & 3);
            const float m0v = mg[c0], m1v = mg[c0 + 1];
            sc[nf][0] = sc[nf][0] * 0.125f + m0v;
            sc[nf][1] = sc[nf][1] * 0.125f + m1v;
            sc[nf][2] = sc[nf][2] * 0.125f + m0v;
            sc[nf][3] = sc[nf][3] * 0.125f + m1v;
        }

        // online softmax (rows split q / q+8, key dim over lanes L&3)
        float tm0 = -1e30f, tm1 = -1e30f;
#pragma unroll
        for (int nf = 0; nf < 8; nf++) {
            tm0 = fmaxf(tm0, fmaxf(sc[nf][0], sc[nf][1]));
            tm1 = fmaxf(tm1, fmaxf(sc[nf][2], sc[nf][3]));
        }
        tm0 = fmaxf(tm0, __shfl_xor_sync(0xffffffffu, tm0, 1));
        tm0 = fmaxf(tm0, __shfl_xor_sync(0xffffffffu, tm0, 2));
        tm1 = fmaxf(tm1, __shfl_xor_sync(0xffffffffu, tm1, 1));
        tm1 = fmaxf(tm1, __shfl_xor_sync(0xffffffffu, tm1, 2));
        const float mn0 = fmaxf(mrow0, tm0), mn1 = fmaxf(mrow1, tm1);
        const float cr0 = __expf(mrow0 - mn0), cr1 = __expf(mrow1 - mn1);
        mrow0 = mn0; mrow1 = mn1;
        float rs0 = 0.f, rs1 = 0.f;
#pragma unroll
        for (int nf = 0; nf < 8; nf++) {
            sc[nf][0] = __expf(sc[nf][0] - mn0); rs0 += sc[nf][0];
            sc[nf][1] = __expf(sc[nf][1] - mn0); rs0 += sc[nf][1];
            sc[nf][2] = __expf(sc[nf][2] - mn1); rs1 += sc[nf][2];
            sc[nf][3] = __expf(sc[nf][3] - mn1); rs1 += sc[nf][3];
        }
        rs0 += __shfl_xor_sync(0xffffffffu, rs0, 1);
        rs0 += __shfl_xor_sync(0xffffffffu, rs0, 2);
        rs1 += __shfl_xor_sync(0xffffffffu, rs1, 1);
        rs1 += __shfl_xor_sync(0xffffffffu, rs1, 2);
        lrow0 = lrow0 * cr0 + rs0;
        lrow1 = lrow1 * cr1 + rs1;
#pragma unroll
        for (int df = 0; df < 8; df++) {
            oacc[df][0] *= cr0; oacc[df][1] *= cr0;
            oacc[df][2] *= cr1; oacc[df][3] *= cr1;
        }

        // P @ V
#pragma unroll
        for (int ks = 0; ks < 4; ks++) {
            uint32_t ah0, ah1, ah2, ah3, al0, al1, al2, al3;
            pack_hl2(sc[2*ks][0],   sc[2*ks][1],   ah0, al0);
            pack_hl2(sc[2*ks][2],   sc[2*ks][3],   ah1, al1);
            pack_hl2(sc[2*ks+1][0], sc[2*ks+1][1], ah2, al2);
            pack_hl2(sc[2*ks+1][2], sc[2*ks+1][3], ah3, al3);
            uint32_t vbh[4][4], vbl[4][4];
#pragma unroll
            for (int dh = 0; dh < 4; dh++) {
                const int vrow = ks * 16 + (L & 15);
                const int vcol = dh * 16 + ((L >> 4) << 3);
                ldsm4t(smem_u32(sVh + vrow * TSTR + vcol), vbh[dh][0], vbh[dh][1], vbh[dh][2], vbh[dh][3]);
                ldsm4t(smem_u32(sVl + vrow * TSTR + vcol), vbl[dh][0], vbl[dh][1], vbl[dh][2], vbl[dh][3]);
            }
#pragma unroll
            for (int df = 0; df < 8; df++) {
                uint32_t b0h = vbh[df >> 1][(df & 1) * 2], b1h = vbh[df >> 1][(df & 1) * 2 + 1];
                uint32_t b0l = vbl[df >> 1][(df & 1) * 2], b1l = vbl[df >> 1][(df & 1) * 2 + 1];
                mma16816(oacc[df], ah0, ah1, ah2, ah3, b0h, b1h);
                mma16816(oacc[df], ah0, ah1, ah2, ah3, b0l, b1l);
                mma16816(oacc[df], al0, al1, al2, al3, b0h, b1h);
            }
        }

        __syncthreads();
        if (kt + 2 < S_LEN / 64)
            attn_issue_kv(dsm, kh, kl, vh, vl, kt + 2, kt & 1, base, t);
        CP_COMMIT;
    }

    const float inv0 = 1.f / lrow0, inv1 = 1.f / lrow1;
    const int r0 = s0 + w * 16 + (L >> 2);
#pragma unroll
    for (int df = 0; df < 8; df++) {
        const int d = df * 8 + 2 * (L & 3);
        const size_t i0 = (size_t)r0 * ROWB + base + d;
        const size_t i1 = i0 + 8 * ROWB;
        uint32_t hh, ll;
        pack_hl2(oacc[df][0] * inv0, oacc[df][1] * inv0, hh, ll);
        *(uint32_t*)&ch_[i0] = hh; *(uint32_t*)&cl_[i0] = ll;
        pack_hl2(oacc[df][2] * inv1, oacc[df][3] * inv1, hh, ll);
        *(uint32_t*)&ch_[i1] = hh; *(uint32_t*)&cl_[i1] = ll;
    }
}

// =================================================================
// LayerNorm; also emits bf16 hi/lo
// =================================================================
__global__ __launch_bounds__(256)
void ln_kernel(const float* __restrict__ X, const float* __restrict__ gamma,
               const float* __restrict__ beta, float* __restrict__ out,
               bf16* __restrict__ oh, bf16* __restrict__ ol)
{
    const int row = blockIdx.x;
    const int t = threadIdx.x;
    const float* x = X + (size_t)row * HID;

    float4 v = *(const float4*)(x + t * 4);
    float s  = v.x + v.y + v.z + v.w;
    float sq = v.x*v.x + v.y*v.y + v.z*v.z + v.w*v.w;
#pragma unroll
    for (int off = 16; off; off >>= 1) {
        s  += __shfl_xor_sync(0xffffffffu, s,  off);
        sq += __shfl_xor_sync(0xffffffffu, sq, off);
    }
    __shared__ float ss[8], sqs[8];
    const int lane = t & 31, wid = t >> 5;
    if (lane == 0) { ss[wid] = s; sqs[wid] = sq; }
    __syncthreads();
    float tot = 0.f, totq = 0.f;
#pragma unroll
    for (int i = 0; i < 8; i++) { tot += ss[i]; totq += sqs[i]; }
    const float mean = tot * (1.f/1024.f);
    const float var  = totq * (1.f/1024.f) - mean * mean;
    const float rstd = rsqrtf(var + 1e-12f);

    float4 g  = *(const float4*)(gamma + t * 4);
    float4 bb = *(const float4*)(beta + t * 4);
    float4 o;
    o.x = (v.x - mean) * rstd * g.x + bb.x;
    o.y = (v.y - mean) * rstd * g.y + bb.y;
    o.z = (v.z - mean) * rstd * g.z + bb.z;
    o.w = (v.w - mean) * rstd * g.w + bb.w;
    *(float4*)(out + (size_t)row * HID + t * 4) = o;

    uint32_t h0, l0, h1, l1;
    pack_hl2(o.x, o.y, h0, l0);
    pack_hl2(o.z, o.w, h1, l1);
    const size_t idx = (size_t)row * HID + t * 4;
    *(uint32_t*)&oh[idx]     = h0; *(uint32_t*)&ol[idx]     = l0;
    *(uint32_t*)&oh[idx + 2] = h1; *(uint32_t*)&ol[idx + 2] = l1;
}

// ---------------- conversion kernels ----------------
__global__ void wconv_kernel(const float* __restrict__ w0, const float* __restrict__ w1,
                             const float* __restrict__ w2, const float* __restrict__ w3,
                             bf16* __restrict__ wh, bf16* __restrict__ wl)
{
    const float* src;
    const int m = blockIdx.y;
    if (m == 0) src = w0; else if (m == 1) src = w1; else if (m == 2) src = w2; else src = w3;
    const size_t off = (size_t)m * WELEM;
    for (size_t i = (size_t)blockIdx.x * blockDim.x + threadIdx.x; i < (size_t)WELEM;
         i += (size_t)gridDim.x * blockDim.x) {
        float v = src[i];
        bf16 h = __float2bfloat16(v);
        wh[off + i] = h;
        wl[off + i] = __float2bfloat16(v - __bfloat162float(h));
    }
}

__global__ void xconv_kernel(const float* __restrict__ in, float* __restrict__ xo,
                             bf16* __restrict__ xh, bf16* __restrict__ xl)
{
    for (size_t i = (size_t)blockIdx.x * blockDim.x + threadIdx.x; i < (size_t)NELEM;
         i += (size_t)gridDim.x * blockDim.x) {
        float v = in[i];
        xo[i] = v;
        bf16 h = __float2bfloat16(v);
        xh[i] = h;
        xl[i] = __float2bfloat16(v - __bfloat162float(h));
    }
}

// =================================================================
extern "C" void kernel_launch(void* const* d_in, const int* in_sizes, int n_in,
                              void* d_out, int out_size)
{
    const float* input = (const float*)d_in[0];
    const float* mask  = (const float*)d_in[1];
    const float* Wq = (const float*)d_in[2];
    const float* bq = (const float*)d_in[3];
    const float* Wk = (const float*)d_in[4];
    const float* bk = (const float*)d_in[5];
    const float* Wv = (const float*)d_in[6];
    const float* bv = (const float*)d_in[7];
    const float* Wo = (const float*)d_in[8];
    const float* bo = (const float*)d_in[9];
    const float* gamma = (const float*)d_in[10];
    const float* beta  = (const float*)d_in[11];

    float *x, *y; bf16 *xh, *xl, *qh, *ql, *kh, *kl, *vh, *vl, *ch, *cl, *wh, *wl;
    cudaGetSymbolAddress((void**)&x,  g_x);  cudaGetSymbolAddress((void**)&y,  g_y);
    cudaGetSymbolAddress((void**)&xh, g_xh); cudaGetSymbolAddress((void**)&xl, g_xl);
    cudaGetSymbolAddress((void**)&qh, g_qh); cudaGetSymbolAddress((void**)&ql, g_ql);
    cudaGetSymbolAddress((void**)&kh, g_kh); cudaGetSymbolAddress((void**)&kl, g_kl);
    cudaGetSymbolAddress((void**)&vh, g_vh); cudaGetSymbolAddress((void**)&vl, g_vl);
    cudaGetSymbolAddress((void**)&ch, g_ch); cudaGetSymbolAddress((void**)&cl, g_cl);
    cudaGetSymbolAddress((void**)&wh, g_wh); cudaGetSymbolAddress((void**)&wl, g_wl);

    cudaFuncSetAttribute(attn_bf16,    cudaFuncAttributeMaxDynamicSharedMemorySize, ATTN_SMEM);
    cudaFuncSetAttribute(qkv_kernel,   cudaFuncAttributeMaxDynamicSharedMemorySize, GEMM_SMEM);
    cudaFuncSetAttribute(oproj_kernel, cudaFuncAttributeMaxDynamicSharedMemorySize, GEMM_SMEM);

    wconv_kernel<<<dim3(4096, 4), 256>>>(Wq, Wk, Wv, Wo, wh, wl);
    xconv_kernel<<<4096, 256>>>(input, x, xh, xl);

    for (int l = 0; l < NLAYER; l++) {
        const size_t wq_o = (size_t)(0 * NLAYER + l) * HID * HID;
        const size_t wk_o = (size_t)(1 * NLAYER + l) * HID * HID;
        const size_t wv_o = (size_t)(2 * NLAYER + l) * HID * HID;
        const size_t wo_o = (size_t)(3 * NLAYER + l) * HID * HID;
        const size_t voff = (size_t)l * HID;

        qkv_kernel<<<dim3(8, 32, 3), 256, GEMM_SMEM>>>(
            xh, xl,
            wh + wq_o, wl + wq_o, wh + wk_o, wl + wk_o, wh + wv_o, wl + wv_o,
            bq + voff, bk + voff, bv + voff,
            qh, ql, kh, kl, vh, vl);

        attn_bf16<<<dim3(S_LEN / QT, BATCH * NHEAD), 256, ATTN_SMEM>>>(
            qh, ql, kh, kl, vh, vl, mask, ch, cl);

        oproj_kernel<<<dim3(8, 32), 256, GEMM_SMEM>>>(ch, cl, wh + wo_o, wl + wo_o,
                                                      bo + voff, x, y);

        float* dst = (l == NLAYER - 1) ? (float*)d_out : x;
        ln_kernel<<<M_ROWS, 256>>>(y, gamma + voff, beta + voff, dst, xh, xl);
    }
}

// round 4
// speedup vs baseline: 2.6568x; 1.0995x over previous
#include <cuda_runtime.h>
#include <cuda_bf16.h>
#include <cstdint>

#define S_LEN  2048
#define BATCH  2
#define HID    1024
#define NHEAD  16
#define HDIM   64
#define NLAYER 12
#define M_ROWS (S_LEN*BATCH)   // 4096
#define ROWB   (BATCH*HID)     // 2048
#define NELEM  (M_ROWS*HID)
#define WELEM  (NLAYER*HID*HID)

typedef __nv_bfloat16 bf16;

// ---------------- scratch ----------------
__device__ float g_x [NELEM];
__device__ float g_y [NELEM];
__device__ bf16  g_xh[NELEM], g_xl[NELEM];
__device__ bf16  g_qh[NELEM], g_ql[NELEM];
__device__ bf16  g_kh[NELEM], g_kl[NELEM];
__device__ bf16  g_vh[NELEM], g_vl[NELEM];
__device__ bf16  g_ch[NELEM], g_cl[NELEM];
__device__ bf16  g_wh[4ull*WELEM], g_wl[4ull*WELEM];

// ---------------- helpers ----------------
__device__ __forceinline__ uint32_t smem_u32(const void* p) {
    return (uint32_t)__cvta_generic_to_shared(p);
}
__device__ __forceinline__ void cp16(void* s, const void* g) {
    asm volatile("cp.async.cg.shared.global [%0], [%1], 16;"
        :: "r"(smem_u32(s)), "l"(g));
}
#define CP_COMMIT asm volatile("cp.async.commit_group;")
#define CP_WAIT(N) asm volatile("cp.async.wait_group %0;" :: "n"(N))

__device__ __forceinline__ void ldsm4(uint32_t a, uint32_t& r0, uint32_t& r1, uint32_t& r2, uint32_t& r3) {
    asm volatile("ldmatrix.sync.aligned.m8n8.x4.shared.b16 {%0,%1,%2,%3},[%4];"
        : "=r"(r0), "=r"(r1), "=r"(r2), "=r"(r3) : "r"(a));
}
__device__ __forceinline__ void ldsm4t(uint32_t a, uint32_t& r0, uint32_t& r1, uint32_t& r2, uint32_t& r3) {
    asm volatile("ldmatrix.sync.aligned.m8n8.x4.trans.shared.b16 {%0,%1,%2,%3},[%4];"
        : "=r"(r0), "=r"(r1), "=r"(r2), "=r"(r3) : "r"(a));
}
__device__ __forceinline__ void mma16816(float* c, uint32_t a0, uint32_t a1, uint32_t a2, uint32_t a3,
                                         uint32_t b0, uint32_t b1) {
    asm volatile("mma.sync.aligned.m16n8k16.row.col.f32.bf16.bf16.f32 "
        "{%0,%1,%2,%3},{%4,%5,%6,%7},{%8,%9},{%0,%1,%2,%3};"
        : "+f"(c[0]), "+f"(c[1]), "+f"(c[2]), "+f"(c[3])
        : "r"(a0), "r"(a1), "r"(a2), "r"(a3), "r"(b0), "r"(b1));
}
__device__ __forceinline__ float fexp2(float x) {
    float r;
    asm("ex2.approx.ftz.f32 %0, %1;" : "=f"(r) : "f"(x));
    return r;
}
__device__ __forceinline__ uint32_t pack2(bf16 x, bf16 y) {
    __nv_bfloat162 p = __halves2bfloat162(x, y);
    return *reinterpret_cast<uint32_t*>(&p);
}
__device__ __forceinline__ void pack_hl2(float x, float y, uint32_t& hi, uint32_t& lo) {
    bf16 hx = __float2bfloat16(x), hy = __float2bfloat16(y);
    bf16 lx = __float2bfloat16(x - __bfloat162float(hx));
    bf16 ly = __float2bfloat16(y - __bfloat162float(hy));
    hi = pack2(hx, hy); lo = pack2(lx, ly);
}

// =================================================================
// bf16x3 GEMM, cp.async double-buffered.
// block 128x128, 256 thr = 8 warps (2m x 4n), warp 64x32, KT=32
// =================================================================
#define ASTR 56
#define BSTR 136
#define SA_OFF(st,hl) (((st)*2+(hl))*128*ASTR)
#define SB_BASE (4*128*ASTR)
#define SB_OFF(st,hl) (SB_BASE + ((st)*2+(hl))*32*BSTR)
#define GEMM_SMEM ((4*128*ASTR + 4*32*BSTR)*(int)sizeof(bf16))  // 92160

__device__ __forceinline__ void gemm_issue(
    bf16* dsm, const bf16* __restrict__ Ah, const bf16* __restrict__ Al,
    const bf16* __restrict__ Wh, const bf16* __restrict__ Wl,
    int m0, int n0, int k0, int st, int t)
{
    const int ar = t >> 1, ac = (t & 1) * 16;
    const size_t ga = (size_t)(m0 + ar) * HID + k0 + ac;
    bf16* a0 = dsm + SA_OFF(st, 0) + ar * ASTR + ac;
    bf16* a1 = dsm + SA_OFF(st, 1) + ar * ASTR + ac;
    cp16(a0,     Ah + ga); cp16(a0 + 8, Ah + ga + 8);
    cp16(a1,     Al + ga); cp16(a1 + 8, Al + ga + 8);
    const int br = t >> 3, bc = (t & 7) * 16;
    const size_t gb = (size_t)(k0 + br) * HID + n0 + bc;
    bf16* b0 = dsm + SB_OFF(st, 0) + br * BSTR + bc;
    bf16* b1 = dsm + SB_OFF(st, 1) + br * BSTR + bc;
    cp16(b0,     Wh + gb); cp16(b0 + 8, Wh + gb + 8);
    cp16(b1,     Wl + gb); cp16(b1 + 8, Wl + gb + 8);
}

__device__ __forceinline__ void gemm_core_bf3(
    const bf16* __restrict__ Ah, const bf16* __restrict__ Al,
    const bf16* __restrict__ Wh, const bf16* __restrict__ Wl,
    float acc[4][4][4])
{
    extern __shared__ bf16 dsm[];
    const int t = threadIdx.x;
    const int L = t & 31, w = t >> 5;
    const int wm = (w >> 2) * 64, wn = (w & 3) * 32;
    const int m0 = blockIdx.y * 128, n0 = blockIdx.x * 128;

#pragma unroll
    for (int i = 0; i < 4; i++)
#pragma unroll
        for (int j = 0; j < 4; j++)
#pragma unroll
            for (int r = 0; r < 4; r++) acc[i][j][r] = 0.f;

    gemm_issue(dsm, Ah, Al, Wh, Wl, m0, n0, 0,  0, t); CP_COMMIT;
    gemm_issue(dsm, Ah, Al, Wh, Wl, m0, n0, 32, 1, t); CP_COMMIT;

    for (int ko = 0; ko < HID / 32; ko++) {
        CP_WAIT(1);
        __syncthreads();
        const int st = ko & 1;
        const bf16* cA0 = dsm + SA_OFF(st, 0);
        const bf16* cA1 = dsm + SA_OFF(st, 1);
        const bf16* cB0 = dsm + SB_OFF(st, 0);
        const bf16* cB1 = dsm + SB_OFF(st, 1);
#pragma unroll
        for (int ks = 0; ks < 2; ks++) {
            const int kk = ks * 16;
            uint32_t bh[2][4], bl[2][4];
#pragma unroll
            for (int nh = 0; nh < 2; nh++) {
                const int brow = kk + (L & 15);
                const int bcol = wn + nh * 16 + ((L >> 4) << 3);
                ldsm4t(smem_u32(cB0 + brow * BSTR + bcol), bh[nh][0], bh[nh][1], bh[nh][2], bh[nh][3]);
                ldsm4t(smem_u32(cB1 + brow * BSTR + bcol), bl[nh][0], bl[nh][1], bl[nh][2], bl[nh][3]);
            }
#pragma unroll
            for (int mf = 0; mf < 4; mf++) {
                const int arow = wm + mf * 16 + (L & 15);
                const int acol = kk + ((L >> 4) << 3);
                uint32_t a0, a1, a2, a3, e0, e1, e2, e3;
                ldsm4(smem_u32(cA0 + arow * ASTR + acol), a0, a1, a2, a3);
                ldsm4(smem_u32(cA1 + arow * ASTR + acol), e0, e1, e2, e3);
#pragma unroll
                for (int nf = 0; nf < 4; nf++) {
                    uint32_t b0h = bh[nf >> 1][(nf & 1) * 2], b1h = bh[nf >> 1][(nf & 1) * 2 + 1];
                    uint32_t b0l = bl[nf >> 1][(nf & 1) * 2], b1l = bl[nf >> 1][(nf & 1) * 2 + 1];
                    mma16816(acc[mf][nf], a0, a1, a2, a3, b0h, b1h);
                    mma16816(acc[mf][nf], a0, a1, a2, a3, b0l, b1l);
                    mma16816(acc[mf][nf], e0, e1, e2, e3, b0h, b1h);
                }
            }
        }
        __syncthreads();
        if (ko + 2 < HID / 32)
            gemm_issue(dsm, Ah, Al, Wh, Wl, m0, n0, (ko + 2) * 32, st, t);
        CP_COMMIT;
    }
}

__global__ __launch_bounds__(256, 2)
void qkv_kernel(const bf16* __restrict__ xh, const bf16* __restrict__ xl,
                const bf16* __restrict__ wqh, const bf16* __restrict__ wql,
                const bf16* __restrict__ wkh, const bf16* __restrict__ wkl,
                const bf16* __restrict__ wvh, const bf16* __restrict__ wvl,
                const float* __restrict__ bq, const float* __restrict__ bk, const float* __restrict__ bv,
                bf16* __restrict__ qh, bf16* __restrict__ ql,
                bf16* __restrict__ kh, bf16* __restrict__ kl,
                bf16* __restrict__ vh, bf16* __restrict__ vl)
{
    const bf16 *wh, *wl; const float* bias; bf16 *oh, *ol;
    if (blockIdx.z == 0)      { wh = wqh; wl = wql; bias = bq; oh = qh; ol = ql; }
    else if (blockIdx.z == 1) { wh = wkh; wl = wkl; bias = bk; oh = kh; ol = kl; }
    else                      { wh = wvh; wl = wvl; bias = bv; oh = vh; ol = vl; }

    float acc[4][4][4];
    gemm_core_bf3(xh, xl, wh, wl, acc);

    const int t = threadIdx.x, L = t & 31, w = t >> 5;
    const int wm = (w >> 2) * 64, wn = (w & 3) * 32;
    const int m0 = blockIdx.y * 128, n0 = blockIdx.x * 128;
#pragma unroll
    for (int mf = 0; mf < 4; mf++) {
        const int r0 = m0 + wm + mf * 16 + (L >> 2);
#pragma unroll
        for (int nf = 0; nf < 4; nf++) {
            const int c = n0 + wn + nf * 8 + 2 * (L & 3);
            const float b0 = bias[c], b1 = bias[c + 1];
            uint32_t h, l;
            pack_hl2(acc[mf][nf][0] + b0, acc[mf][nf][1] + b1, h, l);
            *(uint32_t*)&oh[(size_t)r0 * HID + c] = h;
            *(uint32_t*)&ol[(size_t)r0 * HID + c] = l;
            pack_hl2(acc[mf][nf][2] + b0, acc[mf][nf][3] + b1, h, l);
            *(uint32_t*)&oh[(size_t)(r0 + 8) * HID + c] = h;
            *(uint32_t*)&ol[(size_t)(r0 + 8) * HID + c] = l;
        }
    }
}

__global__ __launch_bounds__(256, 2)
void oproj_kernel(const bf16* __restrict__ ch_, const bf16* __restrict__ cl_,
                  const bf16* __restrict__ wh, const bf16* __restrict__ wl,
                  const float* __restrict__ bias, const float* __restrict__ res,
                  float* __restrict__ y)
{
    float acc[4][4][4];
    gemm_core_bf3(ch_, cl_, wh, wl, acc);

    const int t = threadIdx.x, L = t & 31, w = t >> 5;
    const int wm = (w >> 2) * 64, wn = (w & 3) * 32;
    const int m0 = blockIdx.y * 128, n0 = blockIdx.x * 128;
#pragma unroll
    for (int mf = 0; mf < 4; mf++) {
        const int r0 = m0 + wm + mf * 16 + (L >> 2);
#pragma unroll
        for (int nf = 0; nf < 4; nf++) {
            const int c = n0 + wn + nf * 8 + 2 * (L & 3);
            const float b0 = bias[c], b1 = bias[c + 1];
            float2 rv0 = *(const float2*)&res[(size_t)r0 * HID + c];
            float2 rv1 = *(const float2*)&res[(size_t)(r0 + 8) * HID + c];
            float2 o0 = { acc[mf][nf][0] + b0 + rv0.x, acc[mf][nf][1] + b1 + rv0.y };
            float2 o1 = { acc[mf][nf][2] + b0 + rv1.x, acc[mf][nf][3] + b1 + rv1.y };
            *(float2*)&y[(size_t)r0 * HID + c]       = o0;
            *(float2*)&y[(size_t)(r0 + 8) * HID + c] = o1;
        }
    }
}

// =================================================================
// Flash attention bf16x3: 256 thr (8 warps), Q-tile 128 (16/warp),
// K-tile 64, cp.async double-buffered K/V, exp2-domain softmax.
// =================================================================
#define TSTR 72
#define QT   128
#define AT_QH 0
#define AT_QL (QT*TSTR)
#define AT_ST(st) (2*QT*TSTR + (st)*4*64*TSTR)
#define AT_KL (64*TSTR)
#define AT_VH (2*64*TSTR)
#define AT_VL (3*64*TSTR)
#define ATTN_SMEM ((2*QT*TSTR + 8*64*TSTR)*(int)sizeof(bf16))  // 110592
#define LOG2E 1.4426950408889634f
#define SCL2  (0.125f * LOG2E)

__device__ __forceinline__ void attn_issue_kv(
    bf16* dsm, const bf16* __restrict__ kh, const bf16* __restrict__ kl,
    const bf16* __restrict__ vh, const bf16* __restrict__ vl,
    int kt, int st, int base, int t)
{
    const int row = t >> 2, c4 = (t & 3) * 16;
    const size_t g = (size_t)(kt * 64 + row) * ROWB + base + c4;
    bf16* s = dsm + AT_ST(st);
    bf16* pk0 = s +          row * TSTR + c4;
    bf16* pk1 = s + AT_KL  + row * TSTR + c4;
    bf16* pv0 = s + AT_VH  + row * TSTR + c4;
    bf16* pv1 = s + AT_VL  + row * TSTR + c4;
    cp16(pk0, kh + g); cp16(pk0 + 8, kh + g + 8);
    cp16(pk1, kl + g); cp16(pk1 + 8, kl + g + 8);
    cp16(pv0, vh + g); cp16(pv0 + 8, vh + g + 8);
    cp16(pv1, vl + g); cp16(pv1 + 8, vl + g + 8);
}

__global__ __launch_bounds__(256, 2)
void attn_bf16(const bf16* __restrict__ qh, const bf16* __restrict__ ql,
               const bf16* __restrict__ kh, const bf16* __restrict__ kl,
               const bf16* __restrict__ vh, const bf16* __restrict__ vl,
               const float* __restrict__ mask,
               bf16* __restrict__ ch_, bf16* __restrict__ cl_)
{
    extern __shared__ bf16 dsm[];
    const int t = threadIdx.x, L = t & 31, w = t >> 5;
    const int s0 = blockIdx.x * QT;
    const int b  = blockIdx.y >> 4, h = blockIdx.y & 15;
    const int base = b * HID + h * HDIM;

    {
        const int row = t >> 1, cc = (t & 1) * 32;
        const size_t g = (size_t)(s0 + row) * ROWB + base + cc;
        bf16* pq0 = dsm + AT_QH + row * TSTR + cc;
        bf16* pq1 = dsm + AT_QL + row * TSTR + cc;
#pragma unroll
        for (int c = 0; c < 4; c++) {
            cp16(pq0 + c * 8, qh + g + c * 8);
            cp16(pq1 + c * 8, ql + g + c * 8);
        }
    }
    CP_COMMIT;
    attn_issue_kv(dsm, kh, kl, vh, vl, 0, 0, base, t); CP_COMMIT;
    attn_issue_kv(dsm, kh, kl, vh, vl, 1, 1, base, t); CP_COMMIT;

    CP_WAIT(2);
    __syncthreads();

    uint32_t qf[2][4][4];
#pragma unroll
    for (int ks = 0; ks < 4; ks++) {
        const int qrow = w * 16 + (L & 15);
        const int qcol = ks * 16 + ((L >> 4) << 3);
        ldsm4(smem_u32(dsm + AT_QH + qrow * TSTR + qcol), qf[0][ks][0], qf[0][ks][1], qf[0][ks][2], qf[0][ks][3]);
        ldsm4(smem_u32(dsm + AT_QL + qrow * TSTR + qcol), qf[1][ks][0], qf[1][ks][1], qf[1][ks][2], qf[1][ks][3]);
    }

    float oacc[8][4];
#pragma unroll
    for (int i = 0; i < 8; i++)
#pragma unroll
        for (int j = 0; j < 4; j++) oacc[i][j] = 0.f;
    float mrow0 = -1e30f, mrow1 = -1e30f, lrow0 = 0.f, lrow1 = 0.f;

    for (int kt = 0; kt < S_LEN / 64; kt++) {
        CP_WAIT(1);
        __syncthreads();
        const bf16* s   = dsm + AT_ST(kt & 1);
        const bf16* sKh = s;
        const bf16* sKl = s + AT_KL;
        const bf16* sVh = s + AT_VH;
        const bf16* sVl = s + AT_VL;

        float sc[8][4];
#pragma unroll
        for (int i = 0; i < 8; i++)
#pragma unroll
            for (int j = 0; j < 4; j++) sc[i][j] = 0.f;

#pragma unroll
        for (int ks = 0; ks < 4; ks++) {
            uint32_t kbh[4][4], kbl[4][4];
#pragma unroll
            for (int nh = 0; nh < 4; nh++) {
                const int krow = nh * 16 + (L & 7) + ((L >> 4) << 3);
                const int kcol = ks * 16 + (((L >> 3) & 1) << 3);
                ldsm4(smem_u32(sKh + krow * TSTR + kcol), kbh[nh][0], kbh[nh][1], kbh[nh][2], kbh[nh][3]);
                ldsm4(smem_u32(sKl + krow * TSTR + kcol), kbl[nh][0], kbl[nh][1], kbl[nh][2], kbl[nh][3]);
            }
#pragma unroll
            for (int nf = 0; nf < 8; nf++) {
                uint32_t b0h = kbh[nf >> 1][(nf & 1) * 2], b1h = kbh[nf >> 1][(nf & 1) * 2 + 1];
                uint32_t b0l = kbl[nf >> 1][(nf & 1) * 2], b1l = kbl[nf >> 1][(nf & 1) * 2 + 1];
                mma16816(sc[nf], qf[0][ks][0], qf[0][ks][1], qf[0][ks][2], qf[0][ks][3], b0h, b1h);
                mma16816(sc[nf], qf[0][ks][0], qf[0][ks][1], qf[0][ks][2], qf[0][ks][3], b0l, b1l);
                mma16816(sc[nf], qf[1][ks][0], qf[1][ks][1], qf[1][ks][2], qf[1][ks][3], b0h, b1h);
            }
        }

        // to exp2 domain: t = raw*0.125*log2e + mask*log2e
        const float* mg = mask + (size_t)b * S_LEN + kt * 64;
#pragma unroll
        for (int nf = 0; nf < 8; nf++) {
            const int c0 = nf * 8 + 2 * (L & 3);
            const float m0v = mg[c0] * LOG2E, m1v = mg[c0 + 1] * LOG2E;
            sc[nf][0] = fmaf(sc[nf][0], SCL2, m0v);
            sc[nf][1] = fmaf(sc[nf][1], SCL2, m1v);
            sc[nf][2] = fmaf(sc[nf][2], SCL2, m0v);
            sc[nf][3] = fmaf(sc[nf][3], SCL2, m1v);
        }

        // online softmax, exp2 domain
        float tm0 = -1e30f, tm1 = -1e30f;
#pragma unroll
        for (int nf = 0; nf < 8; nf++) {
            tm0 = fmaxf(tm0, fmaxf(sc[nf][0], sc[nf][1]));
            tm1 = fmaxf(tm1, fmaxf(sc[nf][2], sc[nf][3]));
        }
        tm0 = fmaxf(tm0, __shfl_xor_sync(0xffffffffu, tm0, 1));
        tm0 = fmaxf(tm0, __shfl_xor_sync(0xffffffffu, tm0, 2));
        tm1 = fmaxf(tm1, __shfl_xor_sync(0xffffffffu, tm1, 1));
        tm1 = fmaxf(tm1, __shfl_xor_sync(0xffffffffu, tm1, 2));
        const float mn0 = fmaxf(mrow0, tm0), mn1 = fmaxf(mrow1, tm1);
        const float cr0 = fexp2(mrow0 - mn0), cr1 = fexp2(mrow1 - mn1);
        mrow0 = mn0; mrow1 = mn1;
        float rs0 = 0.f, rs1 = 0.f;
#pragma unroll
        for (int nf = 0; nf < 8; nf++) {
            sc[nf][0] = fexp2(sc[nf][0] - mn0); rs0 += sc[nf][0];
            sc[nf][1] = fexp2(sc[nf][1] - mn0); rs0 += sc[nf][1];
            sc[nf][2] = fexp2(sc[nf][2] - mn1); rs1 += sc[nf][2];
            sc[nf][3] = fexp2(sc[nf][3] - mn1); rs1 += sc[nf][3];
        }
        rs0 += __shfl_xor_sync(0xffffffffu, rs0, 1);
        rs0 += __shfl_xor_sync(0xffffffffu, rs0, 2);
        rs1 += __shfl_xor_sync(0xffffffffu, rs1, 1);
        rs1 += __shfl_xor_sync(0xffffffffu, rs1, 2);
        lrow0 = lrow0 * cr0 + rs0;
        lrow1 = lrow1 * cr1 + rs1;
#pragma unroll
        for (int df = 0; df < 8; df++) {
            oacc[df][0] *= cr0; oacc[df][1] *= cr0;
            oacc[df][2] *= cr1; oacc[df][3] *= cr1;
        }

        // P @ V
#pragma unroll
        for (int ks = 0; ks < 4; ks++) {
            uint32_t ah0, ah1, ah2, ah3, al0, al1, al2, al3;
            pack_hl2(sc[2*ks][0],   sc[2*ks][1],   ah0, al0);
            pack_hl2(sc[2*ks][2],   sc[2*ks][3],   ah1, al1);
            pack_hl2(sc[2*ks+1][0], sc[2*ks+1][1], ah2, al2);
            pack_hl2(sc[2*ks+1][2], sc[2*ks+1][3], ah3, al3);
            uint32_t vbh[4][4], vbl[4][4];
#pragma unroll
            for (int dh = 0; dh < 4; dh++) {
                const int vrow = ks * 16 + (L & 15);
                const int vcol = dh * 16 + ((L >> 4) << 3);
                ldsm4t(smem_u32(sVh + vrow * TSTR + vcol), vbh[dh][0], vbh[dh][1], vbh[dh][2], vbh[dh][3]);
                ldsm4t(smem_u32(sVl + vrow * TSTR + vcol), vbl[dh][0], vbl[dh][1], vbl[dh][2], vbl[dh][3]);
            }
#pragma unroll
            for (int df = 0; df < 8; df++) {
                uint32_t b0h = vbh[df >> 1][(df & 1) * 2], b1h = vbh[df >> 1][(df & 1) * 2 + 1];
                uint32_t b0l = vbl[df >> 1][(df & 1) * 2], b1l = vbl[df >> 1][(df & 1) * 2 + 1];
                mma16816(oacc[df], ah0, ah1, ah2, ah3, b0h, b1h);
                mma16816(oacc[df], ah0, ah1, ah2, ah3, b0l, b1l);
                mma16816(oacc[df], al0, al1, al2, al3, b0h, b1h);
            }
        }

        __syncthreads();
        if (kt + 2 < S_LEN / 64)
            attn_issue_kv(dsm, kh, kl, vh, vl, kt + 2, kt & 1, base, t);
        CP_COMMIT;
    }

    const float inv0 = 1.f / lrow0, inv1 = 1.f / lrow1;
    const int r0 = s0 + w * 16 + (L >> 2);
#pragma unroll
    for (int df = 0; df < 8; df++) {
        const int d = df * 8 + 2 * (L & 3);
        const size_t i0 = (size_t)r0 * ROWB + base + d;
        const size_t i1 = i0 + 8 * ROWB;
        uint32_t hh, ll;
        pack_hl2(oacc[df][0] * inv0, oacc[df][1] * inv0, hh, ll);
        *(uint32_t*)&ch_[i0] = hh; *(uint32_t*)&cl_[i0] = ll;
        pack_hl2(oacc[df][2] * inv1, oacc[df][3] * inv1, hh, ll);
        *(uint32_t*)&ch_[i1] = hh; *(uint32_t*)&cl_[i1] = ll;
    }
}

// =================================================================
// LayerNorm; also emits bf16 hi/lo
// =================================================================
__global__ __launch_bounds__(256)
void ln_kernel(const float* __restrict__ X, const float* __restrict__ gamma,
               const float* __restrict__ beta, float* __restrict__ out,
               bf16* __restrict__ oh, bf16* __restrict__ ol)
{
    const int row = blockIdx.x;
    const int t = threadIdx.x;
    const float* x = X + (size_t)row * HID;

    float4 v = *(const float4*)(x + t * 4);
    float s  = v.x + v.y + v.z + v.w;
    float sq = v.x*v.x + v.y*v.y + v.z*v.z + v.w*v.w;
#pragma unroll
    for (int off = 16; off; off >>= 1) {
        s  += __shfl_xor_sync(0xffffffffu, s,  off);
        sq += __shfl_xor_sync(0xffffffffu, sq, off);
    }
    __shared__ float ss[8], sqs[8];
    const int lane = t & 31, wid = t >> 5;
    if (lane == 0) { ss[wid] = s; sqs[wid] = sq; }
    __syncthreads();
    float tot = 0.f, totq = 0.f;
#pragma unroll
    for (int i = 0; i < 8; i++) { tot += ss[i]; totq += sqs[i]; }
    const float mean = tot * (1.f/1024.f);
    const float var  = totq * (1.f/1024.f) - mean * mean;
    const float rstd = rsqrtf(var + 1e-12f);

    float4 g  = *(const float4*)(gamma + t * 4);
    float4 bb = *(const float4*)(beta + t * 4);
    float4 o;
    o.x = (v.x - mean) * rstd * g.x + bb.x;
    o.y = (v.y - mean) * rstd * g.y + bb.y;
    o.z = (v.z - mean) * rstd * g.z + bb.z;
    o.w = (v.w - mean) * rstd * g.w + bb.w;
    *(float4*)(out + (size_t)row * HID + t * 4) = o;

    uint32_t h0, l0, h1, l1;
    pack_hl2(o.x, o.y, h0, l0);
    pack_hl2(o.z, o.w, h1, l1);
    const size_t idx = (size_t)row * HID + t * 4;
    *(uint32_t*)&oh[idx]     = h0; *(uint32_t*)&ol[idx]     = l0;
    *(uint32_t*)&oh[idx + 2] = h1; *(uint32_t*)&ol[idx + 2] = l1;
}

// ---------------- conversion kernels ----------------
__global__ void wconv_kernel(const float* __restrict__ w0, const float* __restrict__ w1,
                             const float* __restrict__ w2, const float* __restrict__ w3,
                             bf16* __restrict__ wh, bf16* __restrict__ wl)
{
    const float* src;
    const int m = blockIdx.y;
    if (m == 0) src = w0; else if (m == 1) src = w1; else if (m == 2) src = w2; else src = w3;
    const size_t off = (size_t)m * WELEM;
    for (size_t i = (size_t)blockIdx.x * blockDim.x + threadIdx.x; i < (size_t)WELEM;
         i += (size_t)gridDim.x * blockDim.x) {
        float v = src[i];
        bf16 h = __float2bfloat16(v);
        wh[off + i] = h;
        wl[off + i] = __float2bfloat16(v - __bfloat162float(h));
    }
}

__global__ void xconv_kernel(const float* __restrict__ in, float* __restrict__ xo,
                             bf16* __restrict__ xh, bf16* __restrict__ xl)
{
    for (size_t i = (size_t)blockIdx.x * blockDim.x + threadIdx.x; i < (size_t)NELEM;
         i += (size_t)gridDim.x * blockDim.x) {
        float v = in[i];
        xo[i] = v;
        bf16 h = __float2bfloat16(v);
        xh[i] = h;
        xl[i] = __float2bfloat16(v - __bfloat162float(h));
    }
}

// =================================================================
extern "C" void kernel_launch(void* const* d_in, const int* in_sizes, int n_in,
                              void* d_out, int out_size)
{
    const float* input = (const float*)d_in[0];
    const float* mask  = (const float*)d_in[1];
    const float* Wq = (const float*)d_in[2];
    const float* bq = (const float*)d_in[3];
    const float* Wk = (const float*)d_in[4];
    const float* bk = (const float*)d_in[5];
    const float* Wv = (const float*)d_in[6];
    const float* bv = (const float*)d_in[7];
    const float* Wo = (const float*)d_in[8];
    const float* bo = (const float*)d_in[9];
    const float* gamma = (const float*)d_in[10];
    const float* beta  = (const float*)d_in[11];

    float *x, *y; bf16 *xh, *xl, *qh, *ql, *kh, *kl, *vh, *vl, *ch, *cl, *wh, *wl;
    cudaGetSymbolAddress((void**)&x,  g_x);  cudaGetSymbolAddress((void**)&y,  g_y);
    cudaGetSymbolAddress((void**)&xh, g_xh); cudaGetSymbolAddress((void**)&xl, g_xl);
    cudaGetSymbolAddress((void**)&qh, g_qh); cudaGetSymbolAddress((void**)&ql, g_ql);
    cudaGetSymbolAddress((void**)&kh, g_kh); cudaGetSymbolAddress((void**)&kl, g_kl);
    cudaGetSymbolAddress((void**)&vh, g_vh); cudaGetSymbolAddress((void**)&vl, g_vl);
    cudaGetSymbolAddress((void**)&ch, g_ch); cudaGetSymbolAddress((void**)&cl, g_cl);
    cudaGetSymbolAddress((void**)&wh, g_wh); cudaGetSymbolAddress((void**)&wl, g_wl);

    cudaFuncSetAttribute(attn_bf16,    cudaFuncAttributeMaxDynamicSharedMemorySize, ATTN_SMEM);
    cudaFuncSetAttribute(qkv_kernel,   cudaFuncAttributeMaxDynamicSharedMemorySize, GEMM_SMEM);
    cudaFuncSetAttribute(oproj_kernel, cudaFuncAttributeMaxDynamicSharedMemorySize, GEMM_SMEM);

    wconv_kernel<<<dim3(4096, 4), 256>>>(Wq, Wk, Wv, Wo, wh, wl);
    xconv_kernel<<<4096, 256>>>(input, x, xh, xl);

    for (int l = 0; l < NLAYER; l++) {
        const size_t wq_o = (size_t)(0 * NLAYER + l) * HID * HID;
        const size_t wk_o = (size_t)(1 * NLAYER + l) * HID * HID;
        const size_t wv_o = (size_t)(2 * NLAYER + l) * HID * HID;
        const size_t wo_o = (size_t)(3 * NLAYER + l) * HID * HID;
        const size_t voff = (size_t)l * HID;

        qkv_kernel<<<dim3(8, 32, 3), 256, GEMM_SMEM>>>(
            xh, xl,
            wh + wq_o, wl + wq_o, wh + wk_o, wl + wk_o, wh + wv_o, wl + wv_o,
            bq + voff, bk + voff, bv + voff,
            qh, ql, kh, kl, vh, vl);

        attn_bf16<<<dim3(S_LEN / QT, BATCH * NHEAD), 256, ATTN_SMEM>>>(
            qh, ql, kh, kl, vh, vl, mask, ch, cl);

        oproj_kernel<<<dim3(8, 32), 256, GEMM_SMEM>>>(ch, cl, wh + wo_o, wl + wo_o,
                                                      bo + voff, x, y);

        float* dst = (l == NLAYER - 1) ? (float*)d_out : x;
        ln_kernel<<<M_ROWS, 256>>>(y, gamma + voff, beta + voff, dst, xh, xl);
    }
}

// round 6
// speedup vs baseline: 3.8269x; 1.4404x over previous
#include <cuda_runtime.h>
#include <cuda_fp16.h>
#include <cstdint>

#define S_LEN  2048
#define BATCH  2
#define HID    1024
#define NHEAD  16
#define HDIM   64
#define NLAYER 12
#define M_ROWS (S_LEN*BATCH)   // 4096
#define ROWB   (BATCH*HID)     // 2048
#define NELEM  (M_ROWS*HID)
#define WELEM  (NLAYER*HID*HID)

typedef __half h16;

// ---------------- scratch ----------------
__device__ float g_x [NELEM];
__device__ float g_y [NELEM];
__device__ h16  g_xh[NELEM], g_xl[NELEM];   // LN output split (GEMM A)
__device__ h16  g_qh[NELEM], g_ql[NELEM];   // Q split (pre-scaled)
__device__ h16  g_kh[NELEM];                // K single
__device__ h16  g_vh[NELEM];                // V single
__device__ h16  g_ch[NELEM], g_cl[NELEM];   // ctx split (oproj A)
__device__ h16  g_w [4ull*WELEM];           // weights single fp16

// ---------------- helpers ----------------
__device__ __forceinline__ uint32_t smem_u32(const void* p) {
    return (uint32_t)__cvta_generic_to_shared(p);
}
__device__ __forceinline__ void cp16(void* s, const void* g) {
    asm volatile("cp.async.cg.shared.global [%0], [%1], 16;"
        :: "r"(smem_u32(s)), "l"(g));
}
#define CP_COMMIT asm volatile("cp.async.commit_group;")
#define CP_WAIT(N) asm volatile("cp.async.wait_group %0;" :: "n"(N))

__device__ __forceinline__ void ldsm4(uint32_t a, uint32_t& r0, uint32_t& r1, uint32_t& r2, uint32_t& r3) {
    asm volatile("ldmatrix.sync.aligned.m8n8.x4.shared.b16 {%0,%1,%2,%3},[%4];"
        : "=r"(r0), "=r"(r1), "=r"(r2), "=r"(r3) : "r"(a));
}
__device__ __forceinline__ void ldsm4t(uint32_t a, uint32_t& r0, uint32_t& r1, uint32_t& r2, uint32_t& r3) {
    asm volatile("ldmatrix.sync.aligned.m8n8.x4.trans.shared.b16 {%0,%1,%2,%3},[%4];"
        : "=r"(r0), "=r"(r1), "=r"(r2), "=r"(r3) : "r"(a));
}
__device__ __forceinline__ void mma16816(float* c, uint32_t a0, uint32_t a1, uint32_t a2, uint32_t a3,
                                         uint32_t b0, uint32_t b1) {
    asm volatile("mma.sync.aligned.m16n8k16.row.col.f32.f16.f16.f32 "
        "{%0,%1,%2,%3},{%4,%5,%6,%7},{%8,%9},{%0,%1,%2,%3};"
        : "+f"(c[0]), "+f"(c[1]), "+f"(c[2]), "+f"(c[3])
        : "r"(a0), "r"(a1), "r"(a2), "r"(a3), "r"(b0), "r"(b1));
}
__device__ __forceinline__ float fexp2(float x) {
    float r;
    asm("ex2.approx.ftz.f32 %0, %1;" : "=f"(r) : "f"(x));
    return r;
}
__device__ __forceinline__ uint32_t hpack2(h16 x, h16 y) {
    __half2 p = __halves2half2(x, y);
    return *reinterpret_cast<uint32_t*>(&p);
}
__device__ __forceinline__ void hsplit2(float x, float y, uint32_t& hi, uint32_t& lo) {
    h16 hx = __float2half_rn(x), hy = __float2half_rn(y);
    h16 lx = __float2half_rn(x - __half2float(hx));
    h16 ly = __float2half_rn(y - __half2float(hy));
    hi = hpack2(hx, hy); lo = hpack2(lx, ly);
}

#define LOG2E 1.4426950408889634f
#define SCL2  (0.125f * LOG2E)

// =================================================================
// fp16 split-A GEMM, cp.async double-buffered.
// block 128x128, 256 thr = 8 warps (2m x 4n), warp 64x32, KT=32
// A split hi/lo in smem; B (weights) single. 2 MMAs per acc per k16.
// =================================================================
#define ASTR 56
#define BSTR 136
#define SA_OFF(st,hl) (((st)*2+(hl))*128*ASTR)
#define SB_BASE (4*128*ASTR)
#define SB_OFF(st) (SB_BASE + (st)*32*BSTR)
#define GEMM_SMEM ((4*128*ASTR + 2*32*BSTR)*(int)sizeof(h16))  // 74752

__device__ __forceinline__ void gemm_issue(
    h16* dsm, const h16* __restrict__ Ah, const h16* __restrict__ Al,
    const h16* __restrict__ W, int m0, int n0, int k0, int st, int t)
{
    const int ar = t >> 1, ac = (t & 1) * 16;
    const size_t ga = (size_t)(m0 + ar) * HID + k0 + ac;
    h16* a0 = dsm + SA_OFF(st, 0) + ar * ASTR + ac;
    h16* a1 = dsm + SA_OFF(st, 1) + ar * ASTR + ac;
    cp16(a0,     Ah + ga); cp16(a0 + 8, Ah + ga + 8);
    cp16(a1,     Al + ga); cp16(a1 + 8, Al + ga + 8);
    const int br = t >> 3, bc = (t & 7) * 16;
    const size_t gb = (size_t)(k0 + br) * HID + n0 + bc;
    h16* b0 = dsm + SB_OFF(st) + br * BSTR + bc;
    cp16(b0,     W + gb); cp16(b0 + 8, W + gb + 8);
}

__device__ __forceinline__ void gemm_core(
    const h16* __restrict__ Ah, const h16* __restrict__ Al,
    const h16* __restrict__ W, float acc[4][4][4])
{
    extern __shared__ h16 dsm[];
    const int t = threadIdx.x;
    const int L = t & 31, w = t >> 5;
    const int wm = (w >> 2) * 64, wn = (w & 3) * 32;
    const int m0 = blockIdx.y * 128, n0 = blockIdx.x * 128;

#pragma unroll
    for (int i = 0; i < 4; i++)
#pragma unroll
        for (int j = 0; j < 4; j++)
#pragma unroll
            for (int r = 0; r < 4; r++) acc[i][j][r] = 0.f;

    gemm_issue(dsm, Ah, Al, W, m0, n0, 0,  0, t); CP_COMMIT;
    gemm_issue(dsm, Ah, Al, W, m0, n0, 32, 1, t); CP_COMMIT;

    for (int ko = 0; ko < HID / 32; ko++) {
        CP_WAIT(1);
        __syncthreads();
        const int st = ko & 1;
        const h16* cA0 = dsm + SA_OFF(st, 0);
        const h16* cA1 = dsm + SA_OFF(st, 1);
        const h16* cB  = dsm + SB_OFF(st);
#pragma unroll
        for (int ks = 0; ks < 2; ks++) {
            const int kk = ks * 16;
            uint32_t bb[2][4];
#pragma unroll
            for (int nh = 0; nh < 2; nh++) {
                const int brow = kk + (L & 15);
                const int bcol = wn + nh * 16 + ((L >> 4) << 3);
                ldsm4t(smem_u32(cB + brow * BSTR + bcol), bb[nh][0], bb[nh][1], bb[nh][2], bb[nh][3]);
            }
#pragma unroll
            for (int mf = 0; mf < 4; mf++) {
                const int arow = wm + mf * 16 + (L & 15);
                const int acol = kk + ((L >> 4) << 3);
                uint32_t a0, a1, a2, a3, e0, e1, e2, e3;
                ldsm4(smem_u32(cA0 + arow * ASTR + acol), a0, a1, a2, a3);
                ldsm4(smem_u32(cA1 + arow * ASTR + acol), e0, e1, e2, e3);
#pragma unroll
                for (int nf = 0; nf < 4; nf++) {
                    uint32_t b0 = bb[nf >> 1][(nf & 1) * 2], b1 = bb[nf >> 1][(nf & 1) * 2 + 1];
                    mma16816(acc[mf][nf], a0, a1, a2, a3, b0, b1);
                    mma16816(acc[mf][nf], e0, e1, e2, e3, b0, b1);
                }
            }
        }
        __syncthreads();
        if (ko + 2 < HID / 32)
            gemm_issue(dsm, Ah, Al, W, m0, n0, (ko + 2) * 32, st, t);
        CP_COMMIT;
    }
}

// z=0: Q output, scaled by SCL2 then split hi/lo.
// z=1: K single fp16. z=2: V single fp16.
__global__ __launch_bounds__(256, 2)
void qkv_kernel(const h16* __restrict__ xh, const h16* __restrict__ xl,
                const h16* __restrict__ wbase,
                const float* __restrict__ bq, const float* __restrict__ bk, const float* __restrict__ bv,
                h16* __restrict__ qh, h16* __restrict__ ql,
                h16* __restrict__ kh, h16* __restrict__ vh)
{
    const int z = blockIdx.z;
    const h16* W = wbase + (size_t)z * NLAYER * HID * HID;
    const float* bias = (z == 0) ? bq : (z == 1) ? bk : bv;

    float acc[4][4][4];
    gemm_core(xh, xl, W, acc);

    const int t = threadIdx.x, L = t & 31, w = t >> 5;
    const int wm = (w >> 2) * 64, wn = (w & 3) * 32;
    const int m0 = blockIdx.y * 128, n0 = blockIdx.x * 128;

    if (z == 0) {
#pragma unroll
        for (int mf = 0; mf < 4; mf++) {
            const int r0 = m0 + wm + mf * 16 + (L >> 2);
#pragma unroll
            for (int nf = 0; nf < 4; nf++) {
                const int c = n0 + wn + nf * 8 + 2 * (L & 3);
                const float b0 = bias[c], b1 = bias[c + 1];
                uint32_t h, l;
                hsplit2((acc[mf][nf][0] + b0) * SCL2, (acc[mf][nf][1] + b1) * SCL2, h, l);
                *(uint32_t*)&qh[(size_t)r0 * HID + c] = h;
                *(uint32_t*)&ql[(size_t)r0 * HID + c] = l;
                hsplit2((acc[mf][nf][2] + b0) * SCL2, (acc[mf][nf][3] + b1) * SCL2, h, l);
                *(uint32_t*)&qh[(size_t)(r0 + 8) * HID + c] = h;
                *(uint32_t*)&ql[(size_t)(r0 + 8) * HID + c] = l;
            }
        }
    } else {
        h16* out = (z == 1) ? kh : vh;
#pragma unroll
        for (int mf = 0; mf < 4; mf++) {
            const int r0 = m0 + wm + mf * 16 + (L >> 2);
#pragma unroll
            for (int nf = 0; nf < 4; nf++) {
                const int c = n0 + wn + nf * 8 + 2 * (L & 3);
                const float b0 = bias[c], b1 = bias[c + 1];
                *(uint32_t*)&out[(size_t)r0 * HID + c] =
                    hpack2(__float2half_rn(acc[mf][nf][0] + b0), __float2half_rn(acc[mf][nf][1] + b1));
                *(uint32_t*)&out[(size_t)(r0 + 8) * HID + c] =
                    hpack2(__float2half_rn(acc[mf][nf][2] + b0), __float2half_rn(acc[mf][nf][3] + b1));
            }
        }
    }
}

__global__ __launch_bounds__(256, 2)
void oproj_kernel(const h16* __restrict__ ch_, const h16* __restrict__ cl_,
                  const h16* __restrict__ W,
                  const float* __restrict__ bias, const float* __restrict__ res,
                  float* __restrict__ y)
{
    float acc[4][4][4];
    gemm_core(ch_, cl_, W, acc);

    const int t = threadIdx.x, L = t & 31, w = t >> 5;
    const int wm = (w >> 2) * 64, wn = (w & 3) * 32;
    const int m0 = blockIdx.y * 128, n0 = blockIdx.x * 128;
#pragma unroll
    for (int mf = 0; mf < 4; mf++) {
        const int r0 = m0 + wm + mf * 16 + (L >> 2);
#pragma unroll
        for (int nf = 0; nf < 4; nf++) {
            const int c = n0 + wn + nf * 8 + 2 * (L & 3);
            const float b0 = bias[c], b1 = bias[c + 1];
            float2 rv0 = *(const float2*)&res[(size_t)r0 * HID + c];
            float2 rv1 = *(const float2*)&res[(size_t)(r0 + 8) * HID + c];
            float2 o0 = { acc[mf][nf][0] + b0 + rv0.x, acc[mf][nf][1] + b1 + rv0.y };
            float2 o1 = { acc[mf][nf][2] + b0 + rv1.x, acc[mf][nf][3] + b1 + rv1.y };
            *(float2*)&y[(size_t)r0 * HID + c]       = o0;
            *(float2*)&y[(size_t)(r0 + 8) * HID + c] = o1;
        }
    }
}

// =================================================================
// Flash attention fp16 split-A: 256 thr (8 warps), Q-tile 128,
// K-tile 64, cp.async double-buffered K/V (single arrays).
// Q pre-scaled by 0.125*log2e -> scores directly in exp2 domain.
// =================================================================
#define TSTR 72
#define QT   128
#define AT_QH 0
#define AT_QL (QT*TSTR)
#define AT_ST(st) (2*QT*TSTR + (st)*2*64*TSTR)
#define AT_V  (64*TSTR)
#define ATTN_SMEM ((2*QT*TSTR + 4*64*TSTR)*(int)sizeof(h16))  // 73728

__device__ __forceinline__ void attn_issue_kv(
    h16* dsm, const h16* __restrict__ kh, const h16* __restrict__ vh,
    int kt, int st, int base, int t)
{
    const int row = t >> 2, c4 = (t & 3) * 16;
    const size_t g = (size_t)(kt * 64 + row) * ROWB + base + c4;
    h16* s = dsm + AT_ST(st);
    h16* pk = s +        row * TSTR + c4;
    h16* pv = s + AT_V + row * TSTR + c4;
    cp16(pk, kh + g); cp16(pk + 8, kh + g + 8);
    cp16(pv, vh + g); cp16(pv + 8, vh + g + 8);
}

__global__ __launch_bounds__(256, 2)
void attn_f16(const h16* __restrict__ qh, const h16* __restrict__ ql,
              const h16* __restrict__ kh, const h16* __restrict__ vh,
              const float* __restrict__ mask,
              h16* __restrict__ ch_, h16* __restrict__ cl_)
{
    extern __shared__ h16 dsm[];
    const int t = threadIdx.x, L = t & 31, w = t >> 5;
    const int s0 = blockIdx.x * QT;
    const int b  = blockIdx.y >> 4, h = blockIdx.y & 15;
    const int base = b * HID + h * HDIM;

    {
        const int row = t >> 1, cc = (t & 1) * 32;
        const size_t g = (size_t)(s0 + row) * ROWB + base + cc;
        h16* pq0 = dsm + AT_QH + row * TSTR + cc;
        h16* pq1 = dsm + AT_QL + row * TSTR + cc;
#pragma unroll
        for (int c = 0; c < 4; c++) {
            cp16(pq0 + c * 8, qh + g + c * 8);
            cp16(pq1 + c * 8, ql + g + c * 8);
        }
    }
    CP_COMMIT;
    attn_issue_kv(dsm, kh, vh, 0, 0, base, t); CP_COMMIT;
    attn_issue_kv(dsm, kh, vh, 1, 1, base, t); CP_COMMIT;

    CP_WAIT(2);
    __syncthreads();

    uint32_t qf[2][4][4];
#pragma unroll
    for (int ks = 0; ks < 4; ks++) {
        const int qrow = w * 16 + (L & 15);
        const int qcol = ks * 16 + ((L >> 4) << 3);
        ldsm4(smem_u32(dsm + AT_QH + qrow * TSTR + qcol), qf[0][ks][0], qf[0][ks][1], qf[0][ks][2], qf[0][ks][3]);
        ldsm4(smem_u32(dsm + AT_QL + qrow * TSTR + qcol), qf[1][ks][0], qf[1][ks][1], qf[1][ks][2], qf[1][ks][3]);
    }

    float oacc[8][4];
#pragma unroll
    for (int i = 0; i < 8; i++)
#pragma unroll
        for (int j = 0; j < 4; j++) oacc[i][j] = 0.f;
    float mrow0 = -1e30f, mrow1 = -1e30f, lrow0 = 0.f, lrow1 = 0.f;

    for (int kt = 0; kt < S_LEN / 64; kt++) {
        CP_WAIT(1);
        __syncthreads();
        const h16* s  = dsm + AT_ST(kt & 1);
        const h16* sK = s;
        const h16* sV = s + AT_V;

        float sc[8][4];
#pragma unroll
        for (int i = 0; i < 8; i++)
#pragma unroll
            for (int j = 0; j < 4; j++) sc[i][j] = 0.f;

#pragma unroll
        for (int ks = 0; ks < 4; ks++) {
            uint32_t kb[4][4];
#pragma unroll
            for (int nh = 0; nh < 4; nh++) {
                const int krow = nh * 16 + (L & 7) + ((L >> 4) << 3);
                const int kcol = ks * 16 + (((L >> 3) & 1) << 3);
                ldsm4(smem_u32(sK + krow * TSTR + kcol), kb[nh][0], kb[nh][1], kb[nh][2], kb[nh][3]);
            }
#pragma unroll
            for (int nf = 0; nf < 8; nf++) {
                uint32_t b0 = kb[nf >> 1][(nf & 1) * 2], b1 = kb[nf >> 1][(nf & 1) * 2 + 1];
                mma16816(sc[nf], qf[0][ks][0], qf[0][ks][1], qf[0][ks][2], qf[0][ks][3], b0, b1);
                mma16816(sc[nf], qf[1][ks][0], qf[1][ks][1], qf[1][ks][2], qf[1][ks][3], b0, b1);
            }
        }

        // scores already in exp2 domain; add mask*log2e
        const float* mg = mask + (size_t)b * S_LEN + kt * 64;
#pragma unroll
        for (int nf = 0; nf < 8; nf++) {
            const int c0 = nf * 8 + 2 * (L & 3);
            const float m0v = mg[c0] * LOG2E, m1v = mg[c0 + 1] * LOG2E;
            sc[nf][0] += m0v; sc[nf][1] += m1v;
            sc[nf][2] += m0v; sc[nf][3] += m1v;
        }

        float tm0 = -1e30f, tm1 = -1e30f;
#pragma unroll
        for (int nf = 0; nf < 8; nf++) {
            tm0 = fmaxf(tm0, fmaxf(sc[nf][0], sc[nf][1]));
            tm1 = fmaxf(tm1, fmaxf(sc[nf][2], sc[nf][3]));
        }
        tm0 = fmaxf(tm0, __shfl_xor_sync(0xffffffffu, tm0, 1));
        tm0 = fmaxf(tm0, __shfl_xor_sync(0xffffffffu, tm0, 2));
        tm1 = fmaxf(tm1, __shfl_xor_sync(0xffffffffu, tm1, 1));
        tm1 = fmaxf(tm1, __shfl_xor_sync(0xffffffffu, tm1, 2));
        const float mn0 = fmaxf(mrow0, tm0), mn1 = fmaxf(mrow1, tm1);
        const float cr0 = fexp2(mrow0 - mn0), cr1 = fexp2(mrow1 - mn1);
        mrow0 = mn0; mrow1 = mn1;
        float rs0 = 0.f, rs1 = 0.f;
#pragma unroll
        for (int nf = 0; nf < 8; nf++) {
            sc[nf][0] = fexp2(sc[nf][0] - mn0); rs0 += sc[nf][0];
            sc[nf][1] = fexp2(sc[nf][1] - mn0); rs0 += sc[nf][1];
            sc[nf][2] = fexp2(sc[nf][2] - mn1); rs1 += sc[nf][2];
            sc[nf][3] = fexp2(sc[nf][3] - mn1); rs1 += sc[nf][3];
        }
        rs0 += __shfl_xor_sync(0xffffffffu, rs0, 1);
        rs0 += __shfl_xor_sync(0xffffffffu, rs0, 2);
        rs1 += __shfl_xor_sync(0xffffffffu, rs1, 1);
        rs1 += __shfl_xor_sync(0xffffffffu, rs1, 2);
        lrow0 = lrow0 * cr0 + rs0;
        lrow1 = lrow1 * cr1 + rs1;
#pragma unroll
        for (int df = 0; df < 8; df++) {
            oacc[df][0] *= cr0; oacc[df][1] *= cr0;
            oacc[df][2] *= cr1; oacc[df][3] *= cr1;
        }

        // P @ V, P split hi/lo fp16
#pragma unroll
        for (int ks = 0; ks < 4; ks++) {
            uint32_t ah0, ah1, ah2, ah3, al0, al1, al2, al3;
            hsplit2(sc[2*ks][0],   sc[2*ks][1],   ah0, al0);
            hsplit2(sc[2*ks][2],   sc[2*ks][3],   ah1, al1);
            hsplit2(sc[2*ks+1][0], sc[2*ks+1][1], ah2, al2);
            hsplit2(sc[2*ks+1][2], sc[2*ks+1][3], ah3, al3);
            uint32_t vb[4][4];
#pragma unroll
            for (int dh = 0; dh < 4; dh++) {
                const int vrow = ks * 16 + (L & 15);
                const int vcol = dh * 16 + ((L >> 4) << 3);
                ldsm4t(smem_u32(sV + vrow * TSTR + vcol), vb[dh][0], vb[dh][1], vb[dh][2], vb[dh][3]);
            }
#pragma unroll
            for (int df = 0; df < 8; df++) {
                uint32_t b0 = vb[df >> 1][(df & 1) * 2], b1 = vb[df >> 1][(df & 1) * 2 + 1];
                mma16816(oacc[df], ah0, ah1, ah2, ah3, b0, b1);
                mma16816(oacc[df], al0, al1, al2, al3, b0, b1);
            }
        }

        __syncthreads();
        if (kt + 2 < S_LEN / 64)
            attn_issue_kv(dsm, kh, vh, kt + 2, kt & 1, base, t);
        CP_COMMIT;
    }

    const float inv0 = 1.f / lrow0, inv1 = 1.f / lrow1;
    const int r0 = s0 + w * 16 + (L >> 2);
#pragma unroll
    for (int df = 0; df < 8; df++) {
        const int d = df * 8 + 2 * (L & 3);
        const size_t i0 = (size_t)r0 * ROWB + base + d;
        const size_t i1 = i0 + 8 * ROWB;
        uint32_t hh, ll;
        hsplit2(oacc[df][0] * inv0, oacc[df][1] * inv0, hh, ll);
        *(uint32_t*)&ch_[i0] = hh; *(uint32_t*)&cl_[i0] = ll;
        hsplit2(oacc[df][2] * inv1, oacc[df][3] * inv1, hh, ll);
        *(uint32_t*)&ch_[i1] = hh; *(uint32_t*)&cl_[i1] = ll;
    }
}

// =================================================================
// LayerNorm; also emits fp16 hi/lo
// =================================================================
__global__ __launch_bounds__(256)
void ln_kernel(const float* __restrict__ X, const float* __restrict__ gamma,
               const float* __restrict__ beta, float* __restrict__ out,
               h16* __restrict__ oh, h16* __restrict__ ol)
{
    const int row = blockIdx.x;
    const int t = threadIdx.x;
    const float* x = X + (size_t)row * HID;

    float4 v = *(const float4*)(x + t * 4);
    float s  = v.x + v.y + v.z + v.w;
    float sq = v.x*v.x + v.y*v.y + v.z*v.z + v.w*v.w;
#pragma unroll
    for (int off = 16; off; off >>= 1) {
        s  += __shfl_xor_sync(0xffffffffu, s,  off);
        sq += __shfl_xor_sync(0xffffffffu, sq, off);
    }
    __shared__ float ss[8], sqs[8];
    const int lane = t & 31, wid = t >> 5;
    if (lane == 0) { ss[wid] = s; sqs[wid] = sq; }
    __syncthreads();
    float tot = 0.f, totq = 0.f;
#pragma unroll
    for (int i = 0; i < 8; i++) { tot += ss[i]; totq += sqs[i]; }
    const float mean = tot * (1.f/1024.f);
    const float var  = totq * (1.f/1024.f) - mean * mean;
    const float rstd = rsqrtf(var + 1e-12f);

    float4 g  = *(const float4*)(gamma + t * 4);
    float4 bb = *(const float4*)(beta + t * 4);
    float4 o;
    o.x = (v.x - mean) * rstd * g.x + bb.x;
    o.y = (v.y - mean) * rstd * g.y + bb.y;
    o.z = (v.z - mean) * rstd * g.z + bb.z;
    o.w = (v.w - mean) * rstd * g.w + bb.w;
    *(float4*)(out + (size_t)row * HID + t * 4) = o;

    uint32_t h0, l0, h1, l1;
    hsplit2(o.x, o.y, h0, l0);
    hsplit2(o.z, o.w, h1, l1);
    const size_t idx = (size_t)row * HID + t * 4;
    *(uint32_t*)&oh[idx]     = h0; *(uint32_t*)&ol[idx]     = l0;
    *(uint32_t*)&oh[idx + 2] = h1; *(uint32_t*)&ol[idx + 2] = l1;
}

// ---------------- conversion kernels ----------------
__global__ void wconv_kernel(const float* __restrict__ w0, const float* __restrict__ w1,
                             const float* __restrict__ w2, const float* __restrict__ w3,
                             h16* __restrict__ wdst)
{
    const float* src;
    const int m = blockIdx.y;
    if (m == 0) src = w0; else if (m == 1) src = w1; else if (m == 2) src = w2; else src = w3;
    const size_t off = (size_t)m * WELEM;
    for (size_t i = (size_t)blockIdx.x * blockDim.x + threadIdx.x; i < (size_t)WELEM;
         i += (size_t)gridDim.x * blockDim.x) {
        wdst[off + i] = __float2half_rn(src[i]);
    }
}

__global__ void xconv_kernel(const float* __restrict__ in, float* __restrict__ xo,
                             h16* __restrict__ xh, h16* __restrict__ xl)
{
    for (size_t i = (size_t)blockIdx.x * blockDim.x + threadIdx.x; i < (size_t)NELEM;
         i += (size_t)gridDim.x * blockDim.x) {
        float v = in[i];
        xo[i] = v;
        h16 h = __float2half_rn(v);
        xh[i] = h;
        xl[i] = __float2half_rn(v - __half2float(h));
    }
}

// =================================================================
extern "C" void kernel_launch(void* const* d_in, const int* in_sizes, int n_in,
                              void* d_out, int out_size)
{
    const float* input = (const float*)d_in[0];
    const float* mask  = (const float*)d_in[1];
    const float* Wq = (const float*)d_in[2];
    const float* bq = (const float*)d_in[3];
    const float* Wk = (const float*)d_in[4];
    const float* bk = (const float*)d_in[5];
    const float* Wv = (const float*)d_in[6];
    const float* bv = (const float*)d_in[7];
    const float* Wo = (const float*)d_in[8];
    const float* bo = (const float*)d_in[9];
    const float* gamma = (const float*)d_in[10];
    const float* beta  = (const float*)d_in[11];

    float *x, *y; h16 *xh, *xl, *qh, *ql, *kh, *vh, *ch, *cl, *wv;
    cudaGetSymbolAddress((void**)&x,  g_x);  cudaGetSymbolAddress((void**)&y,  g_y);
    cudaGetSymbolAddress((void**)&xh, g_xh); cudaGetSymbolAddress((void**)&xl, g_xl);
    cudaGetSymbolAddress((void**)&qh, g_qh); cudaGetSymbolAddress((void**)&ql, g_ql);
    cudaGetSymbolAddress((void**)&kh, g_kh); cudaGetSymbolAddress((void**)&vh, g_vh);
    cudaGetSymbolAddress((void**)&ch, g_ch); cudaGetSymbolAddress((void**)&cl, g_cl);
    cudaGetSymbolAddress((void**)&wv, g_w);

    cudaFuncSetAttribute(attn_f16,     cudaFuncAttributeMaxDynamicSharedMemorySize, ATTN_SMEM);
    cudaFuncSetAttribute(qkv_kernel,   cudaFuncAttributeMaxDynamicSharedMemorySize, GEMM_SMEM);
    cudaFuncSetAttribute(oproj_kernel, cudaFuncAttributeMaxDynamicSharedMemorySize, GEMM_SMEM);

    wconv_kernel<<<dim3(4096, 4), 256>>>(Wq, Wk, Wv, Wo, wv);
    xconv_kernel<<<4096, 256>>>(input, x, xh, xl);

    for (int l = 0; l < NLAYER; l++) {
        const size_t wq_o = (size_t)(0 * NLAYER + l) * HID * HID;
        const size_t wo_o = (size_t)(3 * NLAYER + l) * HID * HID;
        const size_t voff = (size_t)l * HID;

        qkv_kernel<<<dim3(8, 32, 3), 256, GEMM_SMEM>>>(
            xh, xl, wv + wq_o,
            bq + voff, bk + voff, bv + voff,
            qh, ql, kh, vh);

        attn_f16<<<dim3(S_LEN / QT, BATCH * NHEAD), 256, ATTN_SMEM>>>(
            qh, ql, kh, vh, mask, ch, cl);

        oproj_kernel<<<dim3(8, 32), 256, GEMM_SMEM>>>(ch, cl, wv + wo_o,
                                                      bo + voff, x, y);

        float* dst = (l == NLAYER - 1) ? (float*)d_out : x;
        ln_kernel<<<M_ROWS, 256>>>(y, gamma + voff, beta + voff, dst, xh, xl);
    }
}

// round 7
// speedup vs baseline: 6.5417x; 1.7094x over previous
#include <cuda_runtime.h>
#include <cuda_fp16.h>
#include <cstdint>

#define S_LEN  2048
#define BATCH  2
#define HID    1024
#define NHEAD  16
#define HDIM   64
#define NLAYER 12
#define M_ROWS (S_LEN*BATCH)   // 4096
#define ROWB   (BATCH*HID)     // 2048
#define NELEM  (M_ROWS*HID)
#define WELEM  (NLAYER*HID*HID)

typedef __half h16;

// ---------------- scratch ----------------
__device__ float g_x [NELEM];
__device__ float g_y [NELEM];
__device__ h16  g_xh[NELEM];               // LN output fp16 (GEMM A)
__device__ h16  g_qh[NELEM];               // Q (pre-scaled)
__device__ h16  g_kh[NELEM];               // K
__device__ h16  g_vh[NELEM];               // V
__device__ h16  g_ch[NELEM];               // ctx (oproj A)
__device__ h16  g_w [4ull*WELEM];          // weights fp16

// ---------------- helpers ----------------
__device__ __forceinline__ uint32_t smem_u32(const void* p) {
    return (uint32_t)__cvta_generic_to_shared(p);
}
__device__ __forceinline__ void cp16(void* s, const void* g) {
    asm volatile("cp.async.cg.shared.global [%0], [%1], 16;"
        :: "r"(smem_u32(s)), "l"(g));
}
#define CP_COMMIT asm volatile("cp.async.commit_group;")
#define CP_WAIT(N) asm volatile("cp.async.wait_group %0;" :: "n"(N))

__device__ __forceinline__ void ldsm4(uint32_t a, uint32_t& r0, uint32_t& r1, uint32_t& r2, uint32_t& r3) {
    asm volatile("ldmatrix.sync.aligned.m8n8.x4.shared.b16 {%0,%1,%2,%3},[%4];"
        : "=r"(r0), "=r"(r1), "=r"(r2), "=r"(r3) : "r"(a));
}
__device__ __forceinline__ void ldsm4t(uint32_t a, uint32_t& r0, uint32_t& r1, uint32_t& r2, uint32_t& r3) {
    asm volatile("ldmatrix.sync.aligned.m8n8.x4.trans.shared.b16 {%0,%1,%2,%3},[%4];"
        : "=r"(r0), "=r"(r1), "=r"(r2), "=r"(r3) : "r"(a));
}
__device__ __forceinline__ void mma16816(float* c, uint32_t a0, uint32_t a1, uint32_t a2, uint32_t a3,
                                         uint32_t b0, uint32_t b1) {
    asm volatile("mma.sync.aligned.m16n8k16.row.col.f32.f16.f16.f32 "
        "{%0,%1,%2,%3},{%4,%5,%6,%7},{%8,%9},{%0,%1,%2,%3};"
        : "+f"(c[0]), "+f"(c[1]), "+f"(c[2]), "+f"(c[3])
        : "r"(a0), "r"(a1), "r"(a2), "r"(a3), "r"(b0), "r"(b1));
}
__device__ __forceinline__ float fexp2(float x) {
    float r;
    asm("ex2.approx.ftz.f32 %0, %1;" : "=f"(r) : "f"(x));
    return r;
}
__device__ __forceinline__ uint32_t fpack2(float x, float y) {
    __half2 p = __floats2half2_rn(x, y);
    return *reinterpret_cast<uint32_t*>(&p);
}

#define LOG2E 1.4426950408889634f
#define SCL2  (0.125f * LOG2E)

// =================================================================
// fp16 GEMM, cp.async double-buffered.
// block 128x128, 256 thr = 8 warps (2m x 4n), warp 64x32, KT=32
// =================================================================
#define ASTR 56
#define BSTR 136
#define SA_OFF(st) ((st)*128*ASTR)
#define SB_BASE (2*128*ASTR)
#define SB_OFF(st) (SB_BASE + (st)*32*BSTR)
#define GEMM_SMEM ((2*128*ASTR + 2*32*BSTR)*(int)sizeof(h16))  // 46080

__device__ __forceinline__ void gemm_issue(
    h16* dsm, const h16* __restrict__ A, const h16* __restrict__ W,
    int m0, int n0, int k0, int st, int t)
{
    const int ar = t >> 1, ac = (t & 1) * 16;
    const size_t ga = (size_t)(m0 + ar) * HID + k0 + ac;
    h16* a0 = dsm + SA_OFF(st) + ar * ASTR + ac;
    cp16(a0, A + ga); cp16(a0 + 8, A + ga + 8);
    const int br = t >> 3, bc = (t & 7) * 16;
    const size_t gb = (size_t)(k0 + br) * HID + n0 + bc;
    h16* b0 = dsm + SB_OFF(st) + br * BSTR + bc;
    cp16(b0, W + gb); cp16(b0 + 8, W + gb + 8);
}

__device__ __forceinline__ void gemm_core(
    const h16* __restrict__ A, const h16* __restrict__ W, float acc[4][4][4])
{
    extern __shared__ h16 dsm[];
    const int t = threadIdx.x;
    const int L = t & 31, w = t >> 5;
    const int wm = (w >> 2) * 64, wn = (w & 3) * 32;
    const int m0 = blockIdx.y * 128, n0 = blockIdx.x * 128;

#pragma unroll
    for (int i = 0; i < 4; i++)
#pragma unroll
        for (int j = 0; j < 4; j++)
#pragma unroll
            for (int r = 0; r < 4; r++) acc[i][j][r] = 0.f;

    gemm_issue(dsm, A, W, m0, n0, 0,  0, t); CP_COMMIT;
    gemm_issue(dsm, A, W, m0, n0, 32, 1, t); CP_COMMIT;

    for (int ko = 0; ko < HID / 32; ko++) {
        CP_WAIT(1);
        __syncthreads();
        const int st = ko & 1;
        const h16* cA = dsm + SA_OFF(st);
        const h16* cB = dsm + SB_OFF(st);
#pragma unroll
        for (int ks = 0; ks < 2; ks++) {
            const int kk = ks * 16;
            uint32_t bb[2][4];
#pragma unroll
            for (int nh = 0; nh < 2; nh++) {
                const int brow = kk + (L & 15);
                const int bcol = wn + nh * 16 + ((L >> 4) << 3);
                ldsm4t(smem_u32(cB + brow * BSTR + bcol), bb[nh][0], bb[nh][1], bb[nh][2], bb[nh][3]);
            }
#pragma unroll
            for (int mf = 0; mf < 4; mf++) {
                const int arow = wm + mf * 16 + (L & 15);
                const int acol = kk + ((L >> 4) << 3);
                uint32_t a0, a1, a2, a3;
                ldsm4(smem_u32(cA + arow * ASTR + acol), a0, a1, a2, a3);
#pragma unroll
                for (int nf = 0; nf < 4; nf++) {
                    uint32_t b0 = bb[nf >> 1][(nf & 1) * 2], b1 = bb[nf >> 1][(nf & 1) * 2 + 1];
                    mma16816(acc[mf][nf], a0, a1, a2, a3, b0, b1);
                }
            }
        }
        __syncthreads();
        if (ko + 2 < HID / 32)
            gemm_issue(dsm, A, W, m0, n0, (ko + 2) * 32, st, t);
        CP_COMMIT;
    }
}

// z=0: Q output, scaled by SCL2. z=1: K. z=2: V.
__global__ __launch_bounds__(256, 2)
void qkv_kernel(const h16* __restrict__ xh,
                const h16* __restrict__ wbase,
                const float* __restrict__ bq, const float* __restrict__ bk, const float* __restrict__ bv,
                h16* __restrict__ qh, h16* __restrict__ kh, h16* __restrict__ vh)
{
    const int z = blockIdx.z;
    const h16* W = wbase + (size_t)z * NLAYER * HID * HID;
    const float* bias = (z == 0) ? bq : (z == 1) ? bk : bv;
    h16* out = (z == 0) ? qh : (z == 1) ? kh : vh;
    const float scl = (z == 0) ? SCL2 : 1.0f;

    float acc[4][4][4];
    gemm_core(xh, W, acc);

    const int t = threadIdx.x, L = t & 31, w = t >> 5;
    const int wm = (w >> 2) * 64, wn = (w & 3) * 32;
    const int m0 = blockIdx.y * 128, n0 = blockIdx.x * 128;
#pragma unroll
    for (int mf = 0; mf < 4; mf++) {
        const int r0 = m0 + wm + mf * 16 + (L >> 2);
#pragma unroll
        for (int nf = 0; nf < 4; nf++) {
            const int c = n0 + wn + nf * 8 + 2 * (L & 3);
            const float b0 = bias[c], b1 = bias[c + 1];
            *(uint32_t*)&out[(size_t)r0 * HID + c] =
                fpack2((acc[mf][nf][0] + b0) * scl, (acc[mf][nf][1] + b1) * scl);
            *(uint32_t*)&out[(size_t)(r0 + 8) * HID + c] =
                fpack2((acc[mf][nf][2] + b0) * scl, (acc[mf][nf][3] + b1) * scl);
        }
    }
}

__global__ __launch_bounds__(256, 2)
void oproj_kernel(const h16* __restrict__ ch_, const h16* __restrict__ W,
                  const float* __restrict__ bias, const float* __restrict__ res,
                  float* __restrict__ y)
{
    float acc[4][4][4];
    gemm_core(ch_, W, acc);

    const int t = threadIdx.x, L = t & 31, w = t >> 5;
    const int wm = (w >> 2) * 64, wn = (w & 3) * 32;
    const int m0 = blockIdx.y * 128, n0 = blockIdx.x * 128;
#pragma unroll
    for (int mf = 0; mf < 4; mf++) {
        const int r0 = m0 + wm + mf * 16 + (L >> 2);
#pragma unroll
        for (int nf = 0; nf < 4; nf++) {
            const int c = n0 + wn + nf * 8 + 2 * (L & 3);
            const float b0 = bias[c], b1 = bias[c + 1];
            float2 rv0 = *(const float2*)&res[(size_t)r0 * HID + c];
            float2 rv1 = *(const float2*)&res[(size_t)(r0 + 8) * HID + c];
            float2 o0 = { acc[mf][nf][0] + b0 + rv0.x, acc[mf][nf][1] + b1 + rv0.y };
            float2 o1 = { acc[mf][nf][2] + b0 + rv1.x, acc[mf][nf][3] + b1 + rv1.y };
            *(float2*)&y[(size_t)r0 * HID + c]       = o0;
            *(float2*)&y[(size_t)(r0 + 8) * HID + c] = o1;
        }
    }
}

// =================================================================
// Flash attention pure fp16: 256 thr (8 warps), Q-tile 128,
// K-tile 64, cp.async double-buffered K/V.
// Q pre-scaled by 0.125*log2e -> scores in exp2 domain.
// =================================================================
#define TSTR 72
#define QT   128
#define AT_Q  0
#define AT_ST(st) (QT*TSTR + (st)*2*64*TSTR)
#define AT_V  (64*TSTR)
#define ATTN_SMEM ((QT*TSTR + 4*64*TSTR)*(int)sizeof(h16))  // 55296

__device__ __forceinline__ void attn_issue_kv(
    h16* dsm, const h16* __restrict__ kh, const h16* __restrict__ vh,
    int kt, int st, int base, int t)
{
    const int row = t >> 2, c4 = (t & 3) * 16;
    const size_t g = (size_t)(kt * 64 + row) * ROWB + base + c4;
    h16* s = dsm + AT_ST(st);
    h16* pk = s +        row * TSTR + c4;
    h16* pv = s + AT_V + row * TSTR + c4;
    cp16(pk, kh + g); cp16(pk + 8, kh + g + 8);
    cp16(pv, vh + g); cp16(pv + 8, vh + g + 8);
}

__global__ __launch_bounds__(256, 2)
void attn_f16(const h16* __restrict__ qh,
              const h16* __restrict__ kh, const h16* __restrict__ vh,
              const float* __restrict__ mask,
              h16* __restrict__ ch_)
{
    extern __shared__ h16 dsm[];
    const int t = threadIdx.x, L = t & 31, w = t >> 5;
    const int s0 = blockIdx.x * QT;
    const int b  = blockIdx.y >> 4, h = blockIdx.y & 15;
    const int base = b * HID + h * HDIM;

    {
        const int row = t >> 1, cc = (t & 1) * 32;
        const size_t g = (size_t)(s0 + row) * ROWB + base + cc;
        h16* pq = dsm + AT_Q + row * TSTR + cc;
#pragma unroll
        for (int c = 0; c < 4; c++)
            cp16(pq + c * 8, qh + g + c * 8);
    }
    CP_COMMIT;
    attn_issue_kv(dsm, kh, vh, 0, 0, base, t); CP_COMMIT;
    attn_issue_kv(dsm, kh, vh, 1, 1, base, t); CP_COMMIT;

    CP_WAIT(2);
    __syncthreads();

    uint32_t qf[4][4];
#pragma unroll
    for (int ks = 0; ks < 4; ks++) {
        const int qrow = w * 16 + (L & 15);
        const int qcol = ks * 16 + ((L >> 4) << 3);
        ldsm4(smem_u32(dsm + AT_Q + qrow * TSTR + qcol), qf[ks][0], qf[ks][1], qf[ks][2], qf[ks][3]);
    }

    float oacc[8][4];
#pragma unroll
    for (int i = 0; i < 8; i++)
#pragma unroll
        for (int j = 0; j < 4; j++) oacc[i][j] = 0.f;
    float mrow0 = -1e30f, mrow1 = -1e30f, lrow0 = 0.f, lrow1 = 0.f;

    for (int kt = 0; kt < S_LEN / 64; kt++) {
        CP_WAIT(1);
        __syncthreads();
        const h16* s  = dsm + AT_ST(kt & 1);
        const h16* sK = s;
        const h16* sV = s + AT_V;

        float sc[8][4];
#pragma unroll
        for (int i = 0; i < 8; i++)
#pragma unroll
            for (int j = 0; j < 4; j++) sc[i][j] = 0.f;

#pragma unroll
        for (int ks = 0; ks < 4; ks++) {
            uint32_t kb[4][4];
#pragma unroll
            for (int nh = 0; nh < 4; nh++) {
                const int krow = nh * 16 + (L & 7) + ((L >> 4) << 3);
                const int kcol = ks * 16 + (((L >> 3) & 1) << 3);
                ldsm4(smem_u32(sK + krow * TSTR + kcol), kb[nh][0], kb[nh][1], kb[nh][2], kb[nh][3]);
            }
#pragma unroll
            for (int nf = 0; nf < 8; nf++) {
                uint32_t b0 = kb[nf >> 1][(nf & 1) * 2], b1 = kb[nf >> 1][(nf & 1) * 2 + 1];
                mma16816(sc[nf], qf[ks][0], qf[ks][1], qf[ks][2], qf[ks][3], b0, b1);
            }
        }

        // scores in exp2 domain; add mask*log2e
        const float* mg = mask + (size_t)b * S_LEN + kt * 64;
#pragma unroll
        for (int nf = 0; nf < 8; nf++) {
            const int c0 = nf * 8 + 2 * (L & 3);
            const float m0v = mg[c0] * LOG2E, m1v = mg[c0 + 1] * LOG2E;
            sc[nf][0] += m0v; sc[nf][1] += m1v;
            sc[nf][2] += m0v; sc[nf][3] += m1v;
        }

        float tm0 = -1e30f, tm1 = -1e30f;
#pragma unroll
        for (int nf = 0; nf < 8; nf++) {
            tm0 = fmaxf(tm0, fmaxf(sc[nf][0], sc[nf][1]));
            tm1 = fmaxf(tm1, fmaxf(sc[nf][2], sc[nf][3]));
        }
        tm0 = fmaxf(tm0, __shfl_xor_sync(0xffffffffu, tm0, 1));
        tm0 = fmaxf(tm0, __shfl_xor_sync(0xffffffffu, tm0, 2));
        tm1 = fmaxf(tm1, __shfl_xor_sync(0xffffffffu, tm1, 1));
        tm1 = fmaxf(tm1, __shfl_xor_sync(0xffffffffu, tm1, 2));
        const float mn0 = fmaxf(mrow0, tm0), mn1 = fmaxf(mrow1, tm1);
        const float cr0 = fexp2(mrow0 - mn0), cr1 = fexp2(mrow1 - mn1);
        mrow0 = mn0; mrow1 = mn1;
        float rs0 = 0.f, rs1 = 0.f;
#pragma unroll
        for (int nf = 0; nf < 8; nf++) {
            sc[nf][0] = fexp2(sc[nf][0] - mn0); rs0 += sc[nf][0];
            sc[nf][1] = fexp2(sc[nf][1] - mn0); rs0 += sc[nf][1];
            sc[nf][2] = fexp2(sc[nf][2] - mn1); rs1 += sc[nf][2];
            sc[nf][3] = fexp2(sc[nf][3] - mn1); rs1 += sc[nf][3];
        }
        rs0 += __shfl_xor_sync(0xffffffffu, rs0, 1);
        rs0 += __shfl_xor_sync(0xffffffffu, rs0, 2);
        rs1 += __shfl_xor_sync(0xffffffffu, rs1, 1);
        rs1 += __shfl_xor_sync(0xffffffffu, rs1, 2);
        lrow0 = lrow0 * cr0 + rs0;
        lrow1 = lrow1 * cr1 + rs1;
#pragma unroll
        for (int df = 0; df < 8; df++) {
            oacc[df][0] *= cr0; oacc[df][1] *= cr0;
            oacc[df][2] *= cr1; oacc[df][3] *= cr1;
        }

        // P @ V
#pragma unroll
        for (int ks = 0; ks < 4; ks++) {
            uint32_t a0 = fpack2(sc[2*ks][0],   sc[2*ks][1]);
            uint32_t a1 = fpack2(sc[2*ks][2],   sc[2*ks][3]);
            uint32_t a2 = fpack2(sc[2*ks+1][0], sc[2*ks+1][1]);
            uint32_t a3 = fpack2(sc[2*ks+1][2], sc[2*ks+1][3]);
            uint32_t vb[4][4];
#pragma unroll
            for (int dh = 0; dh < 4; dh++) {
                const int vrow = ks * 16 + (L & 15);
                const int vcol = dh * 16 + ((L >> 4) << 3);
                ldsm4t(smem_u32(sV + vrow * TSTR + vcol), vb[dh][0], vb[dh][1], vb[dh][2], vb[dh][3]);
            }
#pragma unroll
            for (int df = 0; df < 8; df++) {
                uint32_t b0 = vb[df >> 1][(df & 1) * 2], b1 = vb[df >> 1][(df & 1) * 2 + 1];
                mma16816(oacc[df], a0, a1, a2, a3, b0, b1);
            }
        }

        __syncthreads();
        if (kt + 2 < S_LEN / 64)
            attn_issue_kv(dsm, kh, vh, kt + 2, kt & 1, base, t);
        CP_COMMIT;
    }

    const float inv0 = 1.f / lrow0, inv1 = 1.f / lrow1;
    const int r0 = s0 + w * 16 + (L >> 2);
#pragma unroll
    for (int df = 0; df < 8; df++) {
        const int d = df * 8 + 2 * (L & 3);
        const size_t i0 = (size_t)r0 * ROWB + base + d;
        const size_t i1 = i0 + 8 * ROWB;
        *(uint32_t*)&ch_[i0] = fpack2(oacc[df][0] * inv0, oacc[df][1] * inv0);
        *(uint32_t*)&ch_[i1] = fpack2(oacc[df][2] * inv1, oacc[df][3] * inv1);
    }
}

// =================================================================
// LayerNorm; also emits fp16
// =================================================================
__global__ __launch_bounds__(256)
void ln_kernel(const float* __restrict__ X, const float* __restrict__ gamma,
               const float* __restrict__ beta, float* __restrict__ out,
               h16* __restrict__ oh)
{
    const int row = blockIdx.x;
    const int t = threadIdx.x;
    const float* x = X + (size_t)row * HID;

    float4 v = *(const float4*)(x + t * 4);
    float s  = v.x + v.y + v.z + v.w;
    float sq = v.x*v.x + v.y*v.y + v.z*v.z + v.w*v.w;
#pragma unroll
    for (int off = 16; off; off >>= 1) {
        s  += __shfl_xor_sync(0xffffffffu, s,  off);
        sq += __shfl_xor_sync(0xffffffffu, sq, off);
    }
    __shared__ float ss[8], sqs[8];
    const int lane = t & 31, wid = t >> 5;
    if (lane == 0) { ss[wid] = s; sqs[wid] = sq; }
    __syncthreads();
    float tot = 0.f, totq = 0.f;
#pragma unroll
    for (int i = 0; i < 8; i++) { tot += ss[i]; totq += sqs[i]; }
    const float mean = tot * (1.f/1024.f);
    const float var  = totq * (1.f/1024.f) - mean * mean;
    const float rstd = rsqrtf(var + 1e-12f);

    float4 g  = *(const float4*)(gamma + t * 4);
    float4 bb = *(const float4*)(beta + t * 4);
    float4 o;
    o.x = (v.x - mean) * rstd * g.x + bb.x;
    o.y = (v.y - mean) * rstd * g.y + bb.y;
    o.z = (v.z - mean) * rstd * g.z + bb.z;
    o.w = (v.w - mean) * rstd * g.w + bb.w;
    *(float4*)(out + (size_t)row * HID + t * 4) = o;

    const size_t idx = (size_t)row * HID + t * 4;
    *(uint32_t*)&oh[idx]     = fpack2(o.x, o.y);
    *(uint32_t*)&oh[idx + 2] = fpack2(o.z, o.w);
}

// ---------------- conversion kernels ----------------
__global__ void wconv_kernel(const float* __restrict__ w0, const float* __restrict__ w1,
                             const float* __restrict__ w2, const float* __restrict__ w3,
                             h16* __restrict__ wdst)
{
    const float* src;
    const int m = blockIdx.y;
    if (m == 0) src = w0; else if (m == 1) src = w1; else if (m == 2) src = w2; else src = w3;
    const size_t off = (size_t)m * WELEM;
    for (size_t i = (size_t)blockIdx.x * blockDim.x + threadIdx.x; i < (size_t)WELEM;
         i += (size_t)gridDim.x * blockDim.x) {
        wdst[off + i] = __float2half_rn(src[i]);
    }
}

__global__ void xconv_kernel(const float* __restrict__ in, float* __restrict__ xo,
                             h16* __restrict__ xh)
{
    for (size_t i = (size_t)blockIdx.x * blockDim.x + threadIdx.x; i < (size_t)NELEM;
         i += (size_t)gridDim.x * blockDim.x) {
        float v = in[i];
        xo[i] = v;
        xh[i] = __float2half_rn(v);
    }
}

// =================================================================
extern "C" void kernel_launch(void* const* d_in, const int* in_sizes, int n_in,
                              void* d_out, int out_size)
{
    const float* input = (const float*)d_in[0];
    const float* mask  = (const float*)d_in[1];
    const float* Wq = (const float*)d_in[2];
    const float* bq = (const float*)d_in[3];
    const float* Wk = (const float*)d_in[4];
    const float* bk = (const float*)d_in[5];
    const float* Wv = (const float*)d_in[6];
    const float* bv = (const float*)d_in[7];
    const float* Wo = (const float*)d_in[8];
    const float* bo = (const float*)d_in[9];
    const float* gamma = (const float*)d_in[10];
    const float* beta  = (const float*)d_in[11];

    float *x, *y; h16 *xh, *qh, *kh, *vh, *ch, *wv;
    cudaGetSymbolAddress((void**)&x,  g_x);  cudaGetSymbolAddress((void**)&y,  g_y);
    cudaGetSymbolAddress((void**)&xh, g_xh);
    cudaGetSymbolAddress((void**)&qh, g_qh);
    cudaGetSymbolAddress((void**)&kh, g_kh); cudaGetSymbolAddress((void**)&vh, g_vh);
    cudaGetSymbolAddress((void**)&ch, g_ch);
    cudaGetSymbolAddress((void**)&wv, g_w);

    cudaFuncSetAttribute(attn_f16,     cudaFuncAttributeMaxDynamicSharedMemorySize, ATTN_SMEM);
    cudaFuncSetAttribute(qkv_kernel,   cudaFuncAttributeMaxDynamicSharedMemorySize, GEMM_SMEM);
    cudaFuncSetAttribute(oproj_kernel, cudaFuncAttributeMaxDynamicSharedMemorySize, GEMM_SMEM);

    wconv_kernel<<<dim3(4096, 4), 256>>>(Wq, Wk, Wv, Wo, wv);
    xconv_kernel<<<4096, 256>>>(input, x, xh);

    for (int l = 0; l < NLAYER; l++) {
        const size_t wq_o = (size_t)(0 * NLAYER + l) * HID * HID;
        const size_t wo_o = (size_t)(3 * NLAYER + l) * HID * HID;
        const size_t voff = (size_t)l * HID;

        qkv_kernel<<<dim3(8, 32, 3), 256, GEMM_SMEM>>>(
            xh, wv + wq_o,
            bq + voff, bk + voff, bv + voff,
            qh, kh, vh);

        attn_f16<<<dim3(S_LEN / QT, BATCH * NHEAD), 256, ATTN_SMEM>>>(
            qh, kh, vh, mask, ch);

        oproj_kernel<<<dim3(8, 32), 256, GEMM_SMEM>>>(ch, wv + wo_o,
                                                      bo + voff, x, y);

        float* dst = (l == NLAYER - 1) ? (float*)d_out : x;
        ln_kernel<<<M_ROWS, 256>>>(y, gamma + voff, beta + voff, dst, xh);
    }
}